// round 3
// baseline (speedup 1.0000x reference)
#include <cuda_runtime.h>

// ---------------------------------------------------------------------------
// Problem constants
// ---------------------------------------------------------------------------
#define TT 1024
#define BB 2
#define EE 1024
#define HH 16
#define DD 64
#define FF 8
#define RR 2047              // 2T-1
#define TBR (TT*BB)          // 2048 rows of [E]
#define RBR (RR*BB)          // 4094 rows of [E]

// ---------------------------------------------------------------------------
// Device scratch (static __device__ arrays; no allocation at runtime)
// ---------------------------------------------------------------------------
__device__ __align__(16) float g_Win [3*EE*EE];   // [3E][E]
__device__ __align__(16) float g_Wpos[EE*EE];     // [E][E]
__device__ __align__(16) float g_Wout[EE*EE];     // [E][E]
__device__ __align__(16) float g_bin [3*EE];
__device__ __align__(16) float g_bpos[EE];
__device__ __align__(16) float g_bout[EE];
__device__ __align__(16) float g_rw  [EE];
__device__ __align__(16) float g_rr  [EE];
__device__ __align__(16) float g_qkv [ (size_t)TBR * 3*EE ]; // [t*B+b][3E]
__device__ __align__(16) float g_rp  [ (size_t)RBR * EE ];   // [u*B+b][E]
__device__ __align__(16) float g_ao  [ (size_t)TBR * EE ];   // [t*B+b][E]

// ---------------------------------------------------------------------------
// Kernel 1: hypernetwork matvec — out[i] = dot8(w[i*8 .. i*8+7], factor)
// One flat index space over all 8 generated tensors.
// ---------------------------------------------------------------------------
#define SEG0 (3*EE*EE)
#define SEG1 (SEG0 + EE*EE)
#define SEG2 (SEG1 + EE*EE)
#define SEG3 (SEG2 + 3*EE)
#define SEG4 (SEG3 + EE)
#define SEG5 (SEG4 + EE)
#define SEG6 (SEG5 + EE)
#define SEG7 (SEG6 + EE)     // total = 5,250,048 (exactly 20508*256)

__global__ void hypernet_kernel(const float* __restrict__ w_in,
                                const float* __restrict__ w_pos,
                                const float* __restrict__ w_out,
                                const float* __restrict__ b_in,
                                const float* __restrict__ b_pos,
                                const float* __restrict__ b_out,
                                const float* __restrict__ rwb,
                                const float* __restrict__ rrb,
                                const float* __restrict__ fac)
{
    __shared__ float fs[8];
    if (threadIdx.x < 8) fs[threadIdx.x] = fac[threadIdx.x];
    __syncthreads();

    int idx = blockIdx.x * blockDim.x + threadIdx.x;
    if (idx >= SEG7) return;

    const float* src; float* dst; int li;
    if      (idx < SEG0) { src = w_in;  dst = g_Win;  li = idx;        }
    else if (idx < SEG1) { src = w_pos; dst = g_Wpos; li = idx - SEG0; }
    else if (idx < SEG2) { src = w_out; dst = g_Wout; li = idx - SEG1; }
    else if (idx < SEG3) { src = b_in;  dst = g_bin;  li = idx - SEG2; }
    else if (idx < SEG4) { src = b_pos; dst = g_bpos; li = idx - SEG3; }
    else if (idx < SEG5) { src = b_out; dst = g_bout; li = idx - SEG4; }
    else if (idx < SEG6) { src = rwb;   dst = g_rw;   li = idx - SEG5; }
    else                 { src = rrb;   dst = g_rr;   li = idx - SEG6; }

    const float4* s4 = reinterpret_cast<const float4*>(src) + (size_t)li * 2;
    float4 a = s4[0];
    float4 b = s4[1];
    dst[li] = a.x*fs[0] + a.y*fs[1] + a.z*fs[2] + a.w*fs[3]
            + b.x*fs[4] + b.y*fs[5] + b.z*fs[6] + b.w*fs[7];
}

// ---------------------------------------------------------------------------
// Kernel 2: SGEMM (NT): C[m][n] = bias[n] + sum_k A[m][k] * Bw[n][k]
// Tiles 128x128x16, 256 threads, 8x8 microtile. `which` selects the bound
// scratch operands so no host-side symbol lookups are needed:
//   which==0: A=Aext(input) , Bw=g_Win , bias=g_bin , C=g_qkv
//   which==1: A=Aext(pos)   , Bw=g_Wpos, bias=g_bpos, C=g_rp
//   which==2: A=g_ao        , Bw=g_Wout, bias=g_bout, C=Cext(d_out)
// ---------------------------------------------------------------------------
__global__ __launch_bounds__(256, 2)
void sgemm_nt(const float* __restrict__ Aext, float* __restrict__ Cext,
              int which, int M, int N, int K)
{
    const float* A; const float* Bw; const float* bias; float* C;
    if (which == 0)      { A = Aext; Bw = g_Win;  bias = g_bin;  C = g_qkv; }
    else if (which == 1) { A = Aext; Bw = g_Wpos; bias = g_bpos; C = g_rp;  }
    else                 { A = g_ao; Bw = g_Wout; bias = g_bout; C = Cext;  }

    __shared__ float As[16][128];
    __shared__ float Bs[16][128];

    const int tid = threadIdx.x;
    const int tx = tid & 15;
    const int ty = tid >> 4;
    const int m0 = blockIdx.y * 128;
    const int n0 = blockIdx.x * 128;

    float acc[8][8];
    #pragma unroll
    for (int a = 0; a < 8; a++)
        #pragma unroll
        for (int c = 0; c < 8; c++) acc[a][c] = 0.f;

    for (int k0 = 0; k0 < K; k0 += 16) {
        #pragma unroll
        for (int i = 0; i < 2; i++) {
            int f   = tid * 2 + i;        // 0..511
            int row = f >> 2;             // 0..127
            int kc  = (f & 3) << 2;       // 0,4,8,12
            float4 va = make_float4(0.f, 0.f, 0.f, 0.f);
            if (m0 + row < M)
                va = *reinterpret_cast<const float4*>(&A[(size_t)(m0 + row) * K + k0 + kc]);
            As[kc + 0][row] = va.x;
            As[kc + 1][row] = va.y;
            As[kc + 2][row] = va.z;
            As[kc + 3][row] = va.w;
            float4 vb = make_float4(0.f, 0.f, 0.f, 0.f);
            if (n0 + row < N)
                vb = *reinterpret_cast<const float4*>(&Bw[(size_t)(n0 + row) * K + k0 + kc]);
            Bs[kc + 0][row] = vb.x;
            Bs[kc + 1][row] = vb.y;
            Bs[kc + 2][row] = vb.z;
            Bs[kc + 3][row] = vb.w;
        }
        __syncthreads();

        #pragma unroll
        for (int k = 0; k < 16; k++) {
            float4 a0 = *reinterpret_cast<const float4*>(&As[k][ty * 8]);
            float4 a1 = *reinterpret_cast<const float4*>(&As[k][ty * 8 + 4]);
            float4 b0 = *reinterpret_cast<const float4*>(&Bs[k][tx * 8]);
            float4 b1 = *reinterpret_cast<const float4*>(&Bs[k][tx * 8 + 4]);
            float ar[8] = {a0.x, a0.y, a0.z, a0.w, a1.x, a1.y, a1.z, a1.w};
            float br[8] = {b0.x, b0.y, b0.z, b0.w, b1.x, b1.y, b1.z, b1.w};
            #pragma unroll
            for (int a = 0; a < 8; a++)
                #pragma unroll
                for (int c = 0; c < 8; c++)
                    acc[a][c] += ar[a] * br[c];
        }
        __syncthreads();
    }

    #pragma unroll
    for (int a = 0; a < 8; a++) {
        int m = m0 + ty * 8 + a;
        if (m >= M) continue;
        #pragma unroll
        for (int cg = 0; cg < 8; cg += 4) {
            int n = n0 + tx * 8 + cg;
            float4 bv = *reinterpret_cast<const float4*>(&bias[n]);
            float4 o  = make_float4(acc[a][cg + 0] + bv.x,
                                    acc[a][cg + 1] + bv.y,
                                    acc[a][cg + 2] + bv.z,
                                    acc[a][cg + 3] + bv.w);
            *reinterpret_cast<float4*>(&C[(size_t)m * N + n]) = o;
        }
    }
}

// ---------------------------------------------------------------------------
// Kernel 3: fused relative-position flash attention.
// Per block: one (b, h, 64-row tile). Loops over 16 column tiles of 64.
// Scores S[i][j] = ( (q_i+rw)·k_j  +  (q_i+rr)·r[j-i+T-1] ) * 1/8
// The rel_shift is the diagonal-band gather: band index = dj - di + 63.
// Online softmax; PV accumulated in registers; normalized at the end.
//
// SMEM (floats):  qw[d][64] | qr[d][64] | k[d][64] | rband[d][128] |
//                 v[64][64] | p[64][64]        => 28672 floats = 112 KB
// ---------------------------------------------------------------------------
#define ATT_SMEM_FLOATS 28672
#define ATT_SMEM_BYTES  (ATT_SMEM_FLOATS * 4)

__global__ __launch_bounds__(256, 1)
void attn_kernel()
{
    extern __shared__ float sm[];
    float* qw = sm;              // [d*64 + i]
    float* qr = sm + 4096;       // [d*64 + i]
    float* ks = sm + 8192;       // [d*64 + j]
    float* rb = sm + 12288;      // [d*128 + u], band width 127 (slot 127 unused)
    float* vs = sm + 20480;      // [j*64 + d]
    float* ps = sm + 24576;      // [i*64 + j]

    const int tid = threadIdx.x;
    const int tx  = tid & 15;
    const int ty  = tid >> 4;
    const int it  = blockIdx.x;      // row-tile (16)
    const int h   = blockIdx.y;      // head (16)
    const int b   = blockIdx.z;      // batch (2)
    const int i0  = it * 64;
    const int hc  = h * DD;          // head column offset

    // ---- load q tile, pre-add rw / rr, store d-major ----
    #pragma unroll
    for (int rep = 0; rep < 4; rep++) {
        int f  = tid + rep * 256;        // 0..1023
        int i  = f >> 4;                 // 0..63
        int d4 = (f & 15) << 2;          // 0,4,...,60
        float4 q = *reinterpret_cast<const float4*>(
            &g_qkv[((size_t)(i0 + i) * BB + b) * (3 * EE) + hc + d4]);
        float4 w = *reinterpret_cast<const float4*>(&g_rw[hc + d4]);
        float4 r = *reinterpret_cast<const float4*>(&g_rr[hc + d4]);
        qw[(d4 + 0) * 64 + i] = q.x + w.x;
        qw[(d4 + 1) * 64 + i] = q.y + w.y;
        qw[(d4 + 2) * 64 + i] = q.z + w.z;
        qw[(d4 + 3) * 64 + i] = q.w + w.w;
        qr[(d4 + 0) * 64 + i] = q.x + r.x;
        qr[(d4 + 1) * 64 + i] = q.y + r.y;
        qr[(d4 + 2) * 64 + i] = q.z + r.z;
        qr[(d4 + 3) * 64 + i] = q.w + r.w;
    }

    float m_i[4], l_i[4], O[4][4];
    #pragma unroll
    for (int a = 0; a < 4; a++) {
        m_i[a] = -1e30f;
        l_i[a] = 0.f;
        #pragma unroll
        for (int c = 0; c < 4; c++) O[a][c] = 0.f;
    }

    const int u0 = tx * 4 - ty * 4 + 60;   // 4-aligned, in [0, 120]

    for (int jt = 0; jt < 16; jt++) {
        const int j0 = jt * 64;
        __syncthreads();   // previous tile's ps/vs reads complete

        // ---- load k (d-major) and v (j-major) ----
        #pragma unroll
        for (int rep = 0; rep < 4; rep++) {
            int f  = tid + rep * 256;
            int j  = f >> 4;
            int d4 = (f & 15) << 2;
            size_t base = ((size_t)(j0 + j) * BB + b) * (3 * EE) + hc + d4;
            float4 kv = *reinterpret_cast<const float4*>(&g_qkv[base + EE]);
            ks[(d4 + 0) * 64 + j] = kv.x;
            ks[(d4 + 1) * 64 + j] = kv.y;
            ks[(d4 + 2) * 64 + j] = kv.z;
            ks[(d4 + 3) * 64 + j] = kv.w;
            float4 vv = *reinterpret_cast<const float4*>(&g_qkv[base + 2 * EE]);
            *reinterpret_cast<float4*>(&vs[j * 64 + d4]) = vv;
        }
        // ---- load r band: u in [0,127), global row rbase+u (always valid) ----
        const int rbase = 1023 + j0 - i0 - 63;
        for (int f = tid; f < 127 * 16; f += 256) {
            int u  = f >> 4;
            int d4 = (f & 15) << 2;
            float4 rv = *reinterpret_cast<const float4*>(
                &g_rp[((size_t)(rbase + u) * BB + b) * EE + hc + d4]);
            rb[(d4 + 0) * 128 + u] = rv.x;
            rb[(d4 + 1) * 128 + u] = rv.y;
            rb[(d4 + 2) * 128 + u] = rv.z;
            rb[(d4 + 3) * 128 + u] = rv.w;
        }
        __syncthreads();

        // ---- scores: AC + BD ----
        float acc[4][4];
        #pragma unroll
        for (int a = 0; a < 4; a++)
            #pragma unroll
            for (int c = 0; c < 4; c++) acc[a][c] = 0.f;

        #pragma unroll 8
        for (int d = 0; d < 64; d++) {
            float4 qa = *reinterpret_cast<const float4*>(&qw[d * 64 + ty * 4]);
            float4 qq = *reinterpret_cast<const float4*>(&qr[d * 64 + ty * 4]);
            float4 kb = *reinterpret_cast<const float4*>(&ks[d * 64 + tx * 4]);
            float4 r0 = *reinterpret_cast<const float4*>(&rb[d * 128 + u0]);
            float4 r1 = *reinterpret_cast<const float4*>(&rb[d * 128 + u0 + 4]);
            float av[4] = {qa.x, qa.y, qa.z, qa.w};
            float qv[4] = {qq.x, qq.y, qq.z, qq.w};
            float kv[4] = {kb.x, kb.y, kb.z, kb.w};
            float rv[8] = {r0.x, r0.y, r0.z, r0.w, r1.x, r1.y, r1.z, r1.w};
            #pragma unroll
            for (int a = 0; a < 4; a++)
                #pragma unroll
                for (int c = 0; c < 4; c++)
                    acc[a][c] += av[a] * kv[c] + qv[a] * rv[c - a + 3];
        }

        // ---- online softmax (rows split across 16 lanes: xor 1,2,4,8) ----
        #pragma unroll
        for (int a = 0; a < 4; a++) {
            float mx = -1e30f;
            #pragma unroll
            for (int c = 0; c < 4; c++) {
                acc[a][c] *= 0.125f;               // 1/sqrt(D)
                mx = fmaxf(mx, acc[a][c]);
            }
            #pragma unroll
            for (int off = 8; off > 0; off >>= 1)
                mx = fmaxf(mx, __shfl_xor_sync(0xffffffffu, mx, off));
            float mnew = fmaxf(m_i[a], mx);
            float corr = __expf(m_i[a] - mnew);
            float p[4]; float psum = 0.f;
            #pragma unroll
            for (int c = 0; c < 4; c++) {
                p[c] = __expf(acc[a][c] - mnew);
                psum += p[c];
            }
            #pragma unroll
            for (int off = 8; off > 0; off >>= 1)
                psum += __shfl_xor_sync(0xffffffffu, psum, off);
            l_i[a] = l_i[a] * corr + psum;
            m_i[a] = mnew;
            #pragma unroll
            for (int c = 0; c < 4; c++) O[a][c] *= corr;
            *reinterpret_cast<float4*>(&ps[(ty * 4 + a) * 64 + tx * 4]) =
                make_float4(p[0], p[1], p[2], p[3]);
        }
        __syncthreads();

        // ---- PV accumulate ----
        #pragma unroll 4
        for (int j4 = 0; j4 < 16; j4++) {
            float4 pa[4];
            #pragma unroll
            for (int a = 0; a < 4; a++)
                pa[a] = *reinterpret_cast<const float4*>(&ps[(ty * 4 + a) * 64 + j4 * 4]);
            float4 vb[4];
            #pragma unroll
            for (int jj = 0; jj < 4; jj++)
                vb[jj] = *reinterpret_cast<const float4*>(&vs[(j4 * 4 + jj) * 64 + tx * 4]);
            #pragma unroll
            for (int a = 0; a < 4; a++) {
                float pr[4] = {pa[a].x, pa[a].y, pa[a].z, pa[a].w};
                #pragma unroll
                for (int jj = 0; jj < 4; jj++) {
                    O[a][0] += pr[jj] * vb[jj].x;
                    O[a][1] += pr[jj] * vb[jj].y;
                    O[a][2] += pr[jj] * vb[jj].z;
                    O[a][3] += pr[jj] * vb[jj].w;
                }
            }
        }
    }

    // ---- normalize + write [T,B,E] ----
    #pragma unroll
    for (int a = 0; a < 4; a++) {
        float inv = 1.0f / l_i[a];
        float4 o = make_float4(O[a][0] * inv, O[a][1] * inv,
                               O[a][2] * inv, O[a][3] * inv);
        *reinterpret_cast<float4*>(
            &g_ao[((size_t)(i0 + ty * 4 + a) * BB + b) * EE + hc + tx * 4]) = o;
    }
}

// ---------------------------------------------------------------------------
// Host launcher (graph-capturable: kernel launches only)
// ---------------------------------------------------------------------------
extern "C" void kernel_launch(void* const* d_in, const int* in_sizes, int n_in,
                              void* d_out, int out_size)
{
    const float* input  = (const float*)d_in[0];   // [T,B,E]
    const float* pos    = (const float*)d_in[1];   // [R,B,E]
    const float* factor = (const float*)d_in[2];   // [F]
    const float* w_in   = (const float*)d_in[3];   // [3EE, F]
    const float* w_pos  = (const float*)d_in[4];   // [EE, F]
    const float* w_out  = (const float*)d_in[5];   // [EE, F]
    const float* b_in   = (const float*)d_in[6];   // [3E, F]
    const float* b_pos  = (const float*)d_in[7];   // [E, F]
    const float* b_out  = (const float*)d_in[8];   // [E, F]
    const float* rwb    = (const float*)d_in[9];   // [E, F]
    const float* rrb    = (const float*)d_in[10];  // [E, F]
    float* out = (float*)d_out;

    cudaFuncSetAttribute(attn_kernel,
                         cudaFuncAttributeMaxDynamicSharedMemorySize,
                         ATT_SMEM_BYTES);

    // 1) hypernetwork: generate all effective weights
    hypernet_kernel<<<SEG7 / 256, 256>>>(w_in, w_pos, w_out, b_in, b_pos, b_out,
                                         rwb, rrb, factor);

    // 2) qkv = input @ W_in^T + b_in   : [2048, 3072]
    sgemm_nt<<<dim3(3072 / 128, 2048 / 128), 256>>>(input, nullptr, 0,
                                                    TBR, 3 * EE, EE);

    // 3) r = pos @ W_pos^T + b_pos     : [4094, 1024]
    sgemm_nt<<<dim3(1024 / 128, (RBR + 127) / 128), 256>>>(pos, nullptr, 1,
                                                           RBR, EE, EE);

    // 4) fused relative attention -> g_ao
    attn_kernel<<<dim3(TT / 64, HH, BB), 256, ATT_SMEM_BYTES>>>();

    // 5) out = ao @ W_out^T + b_out    : [2048, 1024] -> d_out
    sgemm_nt<<<dim3(1024 / 128, 2048 / 128), 256>>>(nullptr, out, 2,
                                                    TBR, EE, EE);
}

// round 7
// speedup vs baseline: 1.5149x; 1.5149x over previous
#include <cuda_runtime.h>
#include <cuda_bf16.h>
#include <cstdint>

// ---------------------------------------------------------------------------
// Problem constants
// ---------------------------------------------------------------------------
#define TT 1024
#define BB 2
#define EE 1024
#define HH 16
#define DD 64
#define RR 2047              // 2T-1
#define TBR (TT*BB)          // 2048 rows of [E]
#define RBR (RR*BB)          // 4094 valid pos rows
#define RPAD 4096            // padded pos rows (multiple of 128)

// ---------------------------------------------------------------------------
// Device scratch (static; no runtime allocation)
// ---------------------------------------------------------------------------
__device__ __align__(16) __nv_bfloat16 g_Win_h [3*EE*EE], g_Win_l [3*EE*EE];
__device__ __align__(16) __nv_bfloat16 g_Wpos_h[EE*EE],   g_Wpos_l[EE*EE];
__device__ __align__(16) __nv_bfloat16 g_Wout_h[EE*EE],   g_Wout_l[EE*EE];
__device__ __align__(16) __nv_bfloat16 g_in_h  [TBR*EE],  g_in_l  [TBR*EE];
__device__ __align__(16) __nv_bfloat16 g_pos_h [(size_t)RPAD*EE], g_pos_l[(size_t)RPAD*EE];
__device__ __align__(16) __nv_bfloat16 g_ao_h  [TBR*EE],  g_ao_l  [TBR*EE];
__device__ __align__(16) float g_bin [3*EE];
__device__ __align__(16) float g_bpos[EE];
__device__ __align__(16) float g_bout[EE];
__device__ __align__(16) float g_rw  [EE];
__device__ __align__(16) float g_rr  [EE];
__device__ __align__(16) float g_qkv [(size_t)TBR * 3*EE]; // [t*B+b][3E]
__device__ __align__(16) float g_rp  [(size_t)RPAD * EE];  // [u*B+b][E]

// ---------------------------------------------------------------------------
// Portable PTX helpers (NO sm_103a-only instructions: ptxas here is sm_103)
// ---------------------------------------------------------------------------
__device__ __forceinline__ uint32_t smem_u32(const void* p) {
    uint32_t a;
    asm("{ .reg .u64 t; cvta.to.shared.u64 t, %1; cvt.u32.u64 %0, t; }"
        : "=r"(a) : "l"(p));
    return a;
}
__device__ __forceinline__ void cp_async16(uint32_t dst, const void* src) {
    asm volatile("cp.async.cg.shared.global [%0], [%1], 16;"
                 :: "r"(dst), "l"(src) : "memory");
}
#define CP_COMMIT()  asm volatile("cp.async.commit_group;" ::: "memory")
#define CP_WAIT1()   asm volatile("cp.async.wait_group 1;" ::: "memory")
#define CP_WAIT0()   asm volatile("cp.async.wait_group 0;" ::: "memory")

#define LDSM4(r, a) asm volatile( \
    "ldmatrix.sync.aligned.m8n8.x4.shared.b16 {%0,%1,%2,%3}, [%4];" \
    : "=r"((r)[0]), "=r"((r)[1]), "=r"((r)[2]), "=r"((r)[3]) : "r"(a))

#define LDSM2(r, a) asm volatile( \
    "ldmatrix.sync.aligned.m8n8.x2.shared.b16 {%0,%1}, [%2];" \
    : "=r"((r)[0]), "=r"((r)[1]) : "r"(a))

#define MMA_BF16(c, a, b) asm volatile( \
    "mma.sync.aligned.m16n8k16.row.col.f32.bf16.bf16.f32 " \
    "{%0,%1,%2,%3}, {%4,%5,%6,%7}, {%8,%9}, {%0,%1,%2,%3};" \
    : "+f"((c)[0]), "+f"((c)[1]), "+f"((c)[2]), "+f"((c)[3]) \
    : "r"((a)[0]), "r"((a)[1]), "r"((a)[2]), "r"((a)[3]), \
      "r"((b)[0]), "r"((b)[1]))

// ---------------------------------------------------------------------------
// Kernel 1: hypernetwork matvec. W segments -> bf16 hi/lo; rest -> fp32.
// ---------------------------------------------------------------------------
#define SEG0 (3*EE*EE)
#define SEG1 (SEG0 + EE*EE)
#define SEG2 (SEG1 + EE*EE)
#define SEG3 (SEG2 + 3*EE)
#define SEG4 (SEG3 + EE)
#define SEG5 (SEG4 + EE)
#define SEG6 (SEG5 + EE)
#define SEG7 (SEG6 + EE)     // total = 5,250,048 = 20508*256

__global__ void hypernet_kernel(const float* __restrict__ w_in,
                                const float* __restrict__ w_pos,
                                const float* __restrict__ w_out,
                                const float* __restrict__ b_in,
                                const float* __restrict__ b_pos,
                                const float* __restrict__ b_out,
                                const float* __restrict__ rwb,
                                const float* __restrict__ rrb,
                                const float* __restrict__ fac)
{
    __shared__ float fs[8];
    if (threadIdx.x < 8) fs[threadIdx.x] = fac[threadIdx.x];
    __syncthreads();

    int idx = blockIdx.x * blockDim.x + threadIdx.x;
    if (idx >= SEG7) return;

    const float* src; int li;
    if      (idx < SEG0) { src = w_in;  li = idx;        }
    else if (idx < SEG1) { src = w_pos; li = idx - SEG0; }
    else if (idx < SEG2) { src = w_out; li = idx - SEG1; }
    else if (idx < SEG3) { src = b_in;  li = idx - SEG2; }
    else if (idx < SEG4) { src = b_pos; li = idx - SEG3; }
    else if (idx < SEG5) { src = b_out; li = idx - SEG4; }
    else if (idx < SEG6) { src = rwb;   li = idx - SEG5; }
    else                 { src = rrb;   li = idx - SEG6; }

    const float4* s4 = reinterpret_cast<const float4*>(src) + (size_t)li * 2;
    float4 a = s4[0];
    float4 b = s4[1];
    float w = a.x*fs[0] + a.y*fs[1] + a.z*fs[2] + a.w*fs[3]
            + b.x*fs[4] + b.y*fs[5] + b.z*fs[6] + b.w*fs[7];

    if (idx < SEG2) {
        __nv_bfloat16 h = __float2bfloat16(w);
        __nv_bfloat16 l = __float2bfloat16(w - __bfloat162float(h));
        if (idx < SEG0)      { g_Win_h [li] = h; g_Win_l [li] = l; }
        else if (idx < SEG1) { g_Wpos_h[li] = h; g_Wpos_l[li] = l; }
        else                 { g_Wout_h[li] = h; g_Wout_l[li] = l; }
    } else {
        float* dst;
        if      (idx < SEG3) dst = g_bin;
        else if (idx < SEG4) dst = g_bpos;
        else if (idx < SEG5) dst = g_bout;
        else if (idx < SEG6) dst = g_rw;
        else                 dst = g_rr;
        dst[li] = w;
    }
}

// ---------------------------------------------------------------------------
// Kernel 1b: split input / pos into bf16 hi/lo (pos padded to 4096 rows)
// ---------------------------------------------------------------------------
#define NIN4  (TBR * EE / 4)          // 524288
#define NPOS4 ((size_t)RPAD * EE / 4) // 1048576
#define NCONV_BLOCKS 6144             // (NIN4+NPOS4)/256

__global__ void convert_kernel(const float* __restrict__ input,
                               const float* __restrict__ pos)
{
    int idx = blockIdx.x * blockDim.x + threadIdx.x;   // float4 index
    float4 v;
    __nv_bfloat16 *dh, *dl;
    size_t o;
    if (idx < NIN4) {
        v = reinterpret_cast<const float4*>(input)[idx];
        dh = g_in_h; dl = g_in_l; o = (size_t)idx * 4;
    } else {
        size_t j = (size_t)idx - NIN4;
        if (j * 4 < (size_t)RBR * EE)
            v = reinterpret_cast<const float4*>(pos)[j];
        else
            v = make_float4(0.f, 0.f, 0.f, 0.f);
        dh = g_pos_h; dl = g_pos_l; o = j * 4;
    }
    __nv_bfloat16 h0 = __float2bfloat16(v.x), h1 = __float2bfloat16(v.y);
    __nv_bfloat16 h2 = __float2bfloat16(v.z), h3 = __float2bfloat16(v.w);
    __nv_bfloat162 hh0; hh0.x = h0; hh0.y = h1;
    __nv_bfloat162 hh1; hh1.x = h2; hh1.y = h3;
    __nv_bfloat162 ll0, ll1;
    ll0.x = __float2bfloat16(v.x - __bfloat162float(h0));
    ll0.y = __float2bfloat16(v.y - __bfloat162float(h1));
    ll1.x = __float2bfloat16(v.z - __bfloat162float(h2));
    ll1.y = __float2bfloat16(v.w - __bfloat162float(h3));
    *reinterpret_cast<__nv_bfloat162*>(&dh[o])     = hh0;
    *reinterpret_cast<__nv_bfloat162*>(&dh[o + 2]) = hh1;
    *reinterpret_cast<__nv_bfloat162*>(&dl[o])     = ll0;
    *reinterpret_cast<__nv_bfloat162*>(&dl[o + 2]) = ll1;
}

// ---------------------------------------------------------------------------
// Kernel 2: HMMA bf16x3 GEMM (NT): C[m][n] = bias[n] + sum_k A[m][k]*B[n][k]
// mma.sync.m16n8k16 (portable sm_80+ PTX — compiles for plain sm_103).
// Tile 128x128, K chunks of 32 bf16, cp.async double buffer.
// 256 threads = 8 warps in a 4(m) x 2(n) grid; warp tile 32x64.
// Products: Ah*Bh + Ah*Bl + Al*Bh (fp32 accum in registers).
// SMEM rows padded to 80B => ldmatrix row starts 20 words apart (conflict-free).
// ---------------------------------------------------------------------------
#define BK 32
#define PITCH 80                 // bytes per smem row: 64 data + 16 pad
#define ARR   (128 * PITCH)      // 10240 bytes per tile array
#define STAGE (4 * ARR)          // Ah | Al | Bh | Bl
#define GEMM_SMEM (2 * STAGE)    // 81920

__global__ __launch_bounds__(256, 1)
void hmma_gemm(float* __restrict__ Cext, int which)
{
    const __nv_bfloat16 *Ah, *Al, *Bh, *Bl;
    const float* bias; float* C; int ldc;
    if (which == 0)      { Ah = g_in_h;  Al = g_in_l;  Bh = g_Win_h;  Bl = g_Win_l;
                           bias = g_bin;  C = g_qkv; ldc = 3*EE; }
    else if (which == 1) { Ah = g_pos_h; Al = g_pos_l; Bh = g_Wpos_h; Bl = g_Wpos_l;
                           bias = g_bpos; C = g_rp;  ldc = EE; }
    else                 { Ah = g_ao_h;  Al = g_ao_l;  Bh = g_Wout_h; Bl = g_Wout_l;
                           bias = g_bout; C = Cext;  ldc = EE; }

    extern __shared__ char smem[];
    const uint32_t sb = smem_u32(smem);

    const int tid  = threadIdx.x;
    const int lane = tid & 31;
    const int wid  = tid >> 5;
    const int wr   = wid >> 1;          // 0..3  (m)
    const int wc   = wid & 1;           // 0..1  (n)
    const int m0   = blockIdx.y * 128;
    const int n0   = blockIdx.x * 128;

    // ---- async load of one K-chunk into stage s ----
    auto load_chunk = [&](int c, int s) {
        const int kc = c * BK;
        #pragma unroll
        for (int it = 0; it < 8; it++) {
            int f   = tid + it * 256;        // 0..2047
            int arr = f >> 9;                // 0..3
            int rem = f & 511;
            int row = rem >> 2;              // 0..127
            int ch  = rem & 3;               // 16B chunk in row
            uint32_t dst = sb + s * STAGE + arr * ARR + row * PITCH + ch * 16;
            const __nv_bfloat16* gp;
            if      (arr == 0) gp = Ah + (size_t)(m0 + row) * EE + kc + ch * 8;
            else if (arr == 1) gp = Al + (size_t)(m0 + row) * EE + kc + ch * 8;
            else if (arr == 2) gp = Bh + (size_t)(n0 + row) * EE + kc + ch * 8;
            else               gp = Bl + (size_t)(n0 + row) * EE + kc + ch * 8;
            cp_async16(dst, gp);
        }
        CP_COMMIT();
    };

    float acc[2][8][4];
    #pragma unroll
    for (int mi = 0; mi < 2; mi++)
        #pragma unroll
        for (int ni = 0; ni < 8; ni++)
            #pragma unroll
            for (int q = 0; q < 4; q++) acc[mi][ni][q] = 0.f;

    load_chunk(0, 0);

    for (int c = 0; c < 32; c++) {
        const int s = c & 1;
        if (c + 1 < 32) { load_chunk(c + 1, s ^ 1); CP_WAIT1(); }
        else            { CP_WAIT0(); }
        __syncthreads();

        const uint32_t aH = sb + s * STAGE;
        const uint32_t aL = aH + ARR;
        const uint32_t bH = aH + 2 * ARR;
        const uint32_t bL = aH + 3 * ARR;
        const int l4 = lane & 15;

        #pragma unroll
        for (int kk = 0; kk < 2; kk++) {         // two k16 halves of BK=32
            const int kb = kk * 32;              // byte offset of k-half

            uint32_t AH[2][4], AL[2][4];
            #pragma unroll
            for (int mi = 0; mi < 2; mi++) {
                uint32_t ro = (wr * 32 + mi * 16 + l4) * PITCH + kb + (lane >> 4) * 16;
                LDSM4(AH[mi], aH + ro);
                LDSM4(AL[mi], aL + ro);
            }
            uint32_t BH[8][2], BL[8][2];
            #pragma unroll
            for (int ni = 0; ni < 8; ni++) {
                uint32_t ro = (wc * 64 + ni * 8 + (l4 & 7)) * PITCH
                            + kb + ((l4 >> 3) & 1) * 16;
                LDSM2(BH[ni], bH + ro);
                LDSM2(BL[ni], bL + ro);
            }
            #pragma unroll
            for (int mi = 0; mi < 2; mi++)
                #pragma unroll
                for (int ni = 0; ni < 8; ni++) {
                    MMA_BF16(acc[mi][ni], AH[mi], BH[ni]);
                    MMA_BF16(acc[mi][ni], AH[mi], BL[ni]);
                    MMA_BF16(acc[mi][ni], AL[mi], BH[ni]);
                }
        }
        __syncthreads();
    }

    // ---- epilogue: frag -> global + bias ----
    #pragma unroll
    for (int mi = 0; mi < 2; mi++) {
        #pragma unroll
        for (int r2 = 0; r2 < 2; r2++) {
            int grow = m0 + wr * 32 + mi * 16 + (lane >> 2) + r2 * 8;
            #pragma unroll
            for (int ni = 0; ni < 8; ni++) {
                int gcol = n0 + wc * 64 + ni * 8 + (lane & 3) * 2;
                float2 bv = *reinterpret_cast<const float2*>(&bias[gcol]);
                float2 o;
                o.x = acc[mi][ni][r2 * 2 + 0] + bv.x;
                o.y = acc[mi][ni][r2 * 2 + 1] + bv.y;
                *reinterpret_cast<float2*>(&C[(size_t)grow * ldc + gcol]) = o;
            }
        }
    }
}

// ---------------------------------------------------------------------------
// Kernel 3: fused relative-position flash attention (unchanged math).
// Output written as bf16 hi/lo for the HMMA out-projection.
// ---------------------------------------------------------------------------
#define ATT_SMEM_FLOATS 28672
#define ATT_SMEM_BYTES  (ATT_SMEM_FLOATS * 4)

__global__ __launch_bounds__(256, 1)
void attn_kernel()
{
    extern __shared__ float sm[];
    float* qw = sm;              // [d*64 + i]
    float* qr = sm + 4096;       // [d*64 + i]
    float* ks = sm + 8192;       // [d*64 + j]
    float* rb = sm + 12288;      // [d*128 + u]
    float* vs = sm + 20480;      // [j*64 + d]
    float* ps = sm + 24576;      // [i*64 + j]

    const int tid = threadIdx.x;
    const int tx  = tid & 15;
    const int ty  = tid >> 4;
    const int it  = blockIdx.x;
    const int h   = blockIdx.y;
    const int b   = blockIdx.z;
    const int i0  = it * 64;
    const int hc  = h * DD;

    #pragma unroll
    for (int rep = 0; rep < 4; rep++) {
        int f  = tid + rep * 256;
        int i  = f >> 4;
        int d4 = (f & 15) << 2;
        float4 q = *reinterpret_cast<const float4*>(
            &g_qkv[((size_t)(i0 + i) * BB + b) * (3 * EE) + hc + d4]);
        float4 w = *reinterpret_cast<const float4*>(&g_rw[hc + d4]);
        float4 r = *reinterpret_cast<const float4*>(&g_rr[hc + d4]);
        qw[(d4 + 0) * 64 + i] = q.x + w.x;
        qw[(d4 + 1) * 64 + i] = q.y + w.y;
        qw[(d4 + 2) * 64 + i] = q.z + w.z;
        qw[(d4 + 3) * 64 + i] = q.w + w.w;
        qr[(d4 + 0) * 64 + i] = q.x + r.x;
        qr[(d4 + 1) * 64 + i] = q.y + r.y;
        qr[(d4 + 2) * 64 + i] = q.z + r.z;
        qr[(d4 + 3) * 64 + i] = q.w + r.w;
    }

    float m_i[4], l_i[4], O[4][4];
    #pragma unroll
    for (int a = 0; a < 4; a++) {
        m_i[a] = -1e30f;
        l_i[a] = 0.f;
        #pragma unroll
        for (int c = 0; c < 4; c++) O[a][c] = 0.f;
    }

    const int u0 = tx * 4 - ty * 4 + 60;

    for (int jt = 0; jt < 16; jt++) {
        const int j0 = jt * 64;
        __syncthreads();

        #pragma unroll
        for (int rep = 0; rep < 4; rep++) {
            int f  = tid + rep * 256;
            int j  = f >> 4;
            int d4 = (f & 15) << 2;
            size_t base = ((size_t)(j0 + j) * BB + b) * (3 * EE) + hc + d4;
            float4 kv = *reinterpret_cast<const float4*>(&g_qkv[base + EE]);
            ks[(d4 + 0) * 64 + j] = kv.x;
            ks[(d4 + 1) * 64 + j] = kv.y;
            ks[(d4 + 2) * 64 + j] = kv.z;
            ks[(d4 + 3) * 64 + j] = kv.w;
            float4 vv = *reinterpret_cast<const float4*>(&g_qkv[base + 2 * EE]);
            *reinterpret_cast<float4*>(&vs[j * 64 + d4]) = vv;
        }
        const int rbase = 1023 + j0 - i0 - 63;
        for (int f = tid; f < 127 * 16; f += 256) {
            int u  = f >> 4;
            int d4 = (f & 15) << 2;
            float4 rv = *reinterpret_cast<const float4*>(
                &g_rp[((size_t)(rbase + u) * BB + b) * EE + hc + d4]);
            rb[(d4 + 0) * 128 + u] = rv.x;
            rb[(d4 + 1) * 128 + u] = rv.y;
            rb[(d4 + 2) * 128 + u] = rv.z;
            rb[(d4 + 3) * 128 + u] = rv.w;
        }
        __syncthreads();

        float acc[4][4];
        #pragma unroll
        for (int a = 0; a < 4; a++)
            #pragma unroll
            for (int c = 0; c < 4; c++) acc[a][c] = 0.f;

        #pragma unroll 8
        for (int d = 0; d < 64; d++) {
            float4 qa = *reinterpret_cast<const float4*>(&qw[d * 64 + ty * 4]);
            float4 qq = *reinterpret_cast<const float4*>(&qr[d * 64 + ty * 4]);
            float4 kb = *reinterpret_cast<const float4*>(&ks[d * 64 + tx * 4]);
            float4 r0 = *reinterpret_cast<const float4*>(&rb[d * 128 + u0]);
            float4 r1 = *reinterpret_cast<const float4*>(&rb[d * 128 + u0 + 4]);
            float av[4] = {qa.x, qa.y, qa.z, qa.w};
            float qv[4] = {qq.x, qq.y, qq.z, qq.w};
            float kv[4] = {kb.x, kb.y, kb.z, kb.w};
            float rv[8] = {r0.x, r0.y, r0.z, r0.w, r1.x, r1.y, r1.z, r1.w};
            #pragma unroll
            for (int a = 0; a < 4; a++)
                #pragma unroll
                for (int c = 0; c < 4; c++)
                    acc[a][c] += av[a] * kv[c] + qv[a] * rv[c - a + 3];
        }

        #pragma unroll
        for (int a = 0; a < 4; a++) {
            float mx = -1e30f;
            #pragma unroll
            for (int c = 0; c < 4; c++) {
                acc[a][c] *= 0.125f;
                mx = fmaxf(mx, acc[a][c]);
            }
            #pragma unroll
            for (int off = 8; off > 0; off >>= 1)
                mx = fmaxf(mx, __shfl_xor_sync(0xffffffffu, mx, off));
            float mnew = fmaxf(m_i[a], mx);
            float corr = __expf(m_i[a] - mnew);
            float p[4]; float psum = 0.f;
            #pragma unroll
            for (int c = 0; c < 4; c++) {
                p[c] = __expf(acc[a][c] - mnew);
                psum += p[c];
            }
            #pragma unroll
            for (int off = 8; off > 0; off >>= 1)
                psum += __shfl_xor_sync(0xffffffffu, psum, off);
            l_i[a] = l_i[a] * corr + psum;
            m_i[a] = mnew;
            #pragma unroll
            for (int c = 0; c < 4; c++) O[a][c] *= corr;
            *reinterpret_cast<float4*>(&ps[(ty * 4 + a) * 64 + tx * 4]) =
                make_float4(p[0], p[1], p[2], p[3]);
        }
        __syncthreads();

        #pragma unroll 4
        for (int j4 = 0; j4 < 16; j4++) {
            float4 pa[4];
            #pragma unroll
            for (int a = 0; a < 4; a++)
                pa[a] = *reinterpret_cast<const float4*>(&ps[(ty * 4 + a) * 64 + j4 * 4]);
            float4 vb[4];
            #pragma unroll
            for (int jj = 0; jj < 4; jj++)
                vb[jj] = *reinterpret_cast<const float4*>(&vs[(j4 * 4 + jj) * 64 + tx * 4]);
            #pragma unroll
            for (int a = 0; a < 4; a++) {
                float pr[4] = {pa[a].x, pa[a].y, pa[a].z, pa[a].w};
                #pragma unroll
                for (int jj = 0; jj < 4; jj++) {
                    O[a][0] += pr[jj] * vb[jj].x;
                    O[a][1] += pr[jj] * vb[jj].y;
                    O[a][2] += pr[jj] * vb[jj].z;
                    O[a][3] += pr[jj] * vb[jj].w;
                }
            }
        }
    }

    // ---- normalize + write ao as bf16 hi/lo for the out-proj GEMM ----
    #pragma unroll
    for (int a = 0; a < 4; a++) {
        float inv = 1.0f / l_i[a];
        float4 o = make_float4(O[a][0] * inv, O[a][1] * inv,
                               O[a][2] * inv, O[a][3] * inv);
        size_t base = ((size_t)(i0 + ty * 4 + a) * BB + b) * EE + hc + tx * 4;
        __nv_bfloat16 h0 = __float2bfloat16(o.x), h1 = __float2bfloat16(o.y);
        __nv_bfloat16 h2 = __float2bfloat16(o.z), h3 = __float2bfloat16(o.w);
        __nv_bfloat162 hh0; hh0.x = h0; hh0.y = h1;
        __nv_bfloat162 hh1; hh1.x = h2; hh1.y = h3;
        __nv_bfloat162 ll0, ll1;
        ll0.x = __float2bfloat16(o.x - __bfloat162float(h0));
        ll0.y = __float2bfloat16(o.y - __bfloat162float(h1));
        ll1.x = __float2bfloat16(o.z - __bfloat162float(h2));
        ll1.y = __float2bfloat16(o.w - __bfloat162float(h3));
        *reinterpret_cast<__nv_bfloat162*>(&g_ao_h[base])     = hh0;
        *reinterpret_cast<__nv_bfloat162*>(&g_ao_h[base + 2]) = hh1;
        *reinterpret_cast<__nv_bfloat162*>(&g_ao_l[base])     = ll0;
        *reinterpret_cast<__nv_bfloat162*>(&g_ao_l[base + 2]) = ll1;
    }
}

// ---------------------------------------------------------------------------
// Host launcher (graph-capturable: kernel launches only)
// ---------------------------------------------------------------------------
extern "C" void kernel_launch(void* const* d_in, const int* in_sizes, int n_in,
                              void* d_out, int out_size)
{
    const float* input  = (const float*)d_in[0];
    const float* pos    = (const float*)d_in[1];
    const float* factor = (const float*)d_in[2];
    const float* w_in   = (const float*)d_in[3];
    const float* w_pos  = (const float*)d_in[4];
    const float* w_out  = (const float*)d_in[5];
    const float* b_in   = (const float*)d_in[6];
    const float* b_pos  = (const float*)d_in[7];
    const float* b_out  = (const float*)d_in[8];
    const float* rwb    = (const float*)d_in[9];
    const float* rrb    = (const float*)d_in[10];
    float* out = (float*)d_out;

    cudaFuncSetAttribute(attn_kernel,
                         cudaFuncAttributeMaxDynamicSharedMemorySize,
                         ATT_SMEM_BYTES);
    cudaFuncSetAttribute(hmma_gemm,
                         cudaFuncAttributeMaxDynamicSharedMemorySize,
                         GEMM_SMEM);

    // 1) hypernetwork (W -> bf16 hi/lo) + input/pos split
    hypernet_kernel<<<SEG7 / 256, 256>>>(w_in, w_pos, w_out, b_in, b_pos, b_out,
                                         rwb, rrb, factor);
    convert_kernel<<<NCONV_BLOCKS, 256>>>(input, pos);

    // 2) qkv = input @ W_in^T + b_in   : [2048, 3072]
    hmma_gemm<<<dim3(3072 / 128, TBR / 128), 256, GEMM_SMEM>>>(nullptr, 0);

    // 3) r = pos @ W_pos^T + b_pos     : [4096(pad), 1024]
    hmma_gemm<<<dim3(EE / 128, RPAD / 128), 256, GEMM_SMEM>>>(nullptr, 1);

    // 4) fused relative attention -> ao (bf16 hi/lo)
    attn_kernel<<<dim3(TT / 64, HH, BB), 256, ATT_SMEM_BYTES>>>();

    // 5) out = ao @ W_out^T + b_out    : [2048, 1024] -> d_out
    hmma_gemm<<<dim3(EE / 128, TBR / 128), 256, GEMM_SMEM>>>(out, 2);
}

// round 8
// speedup vs baseline: 2.3906x; 1.5780x over previous
#include <cuda_runtime.h>
#include <cuda_bf16.h>
#include <cstdint>

// ---------------------------------------------------------------------------
// Problem constants
// ---------------------------------------------------------------------------
#define TT 1024
#define BB 2
#define EE 1024
#define HH 16
#define DD 64
#define RR 2047              // 2T-1
#define TBR (TT*BB)          // 2048 rows of [E]
#define RBR (RR*BB)          // 4094 valid pos rows
#define RPAD 4096            // padded pos rows (multiple of 128)

// ---------------------------------------------------------------------------
// Device scratch (static; no runtime allocation)
// ---------------------------------------------------------------------------
__device__ __align__(16) __nv_bfloat16 g_Win_h [3*EE*EE], g_Win_l [3*EE*EE];
__device__ __align__(16) __nv_bfloat16 g_Wpos_h[EE*EE],   g_Wpos_l[EE*EE];
__device__ __align__(16) __nv_bfloat16 g_Wout_h[EE*EE],   g_Wout_l[EE*EE];
__device__ __align__(16) __nv_bfloat16 g_in_h  [TBR*EE],  g_in_l  [TBR*EE];
__device__ __align__(16) __nv_bfloat16 g_pos_h [(size_t)RPAD*EE], g_pos_l[(size_t)RPAD*EE];
__device__ __align__(16) __nv_bfloat16 g_ao_h  [TBR*EE],  g_ao_l  [TBR*EE];
// qkv / rp now live as bf16 hi/lo (produced by the GEMM epilogue directly)
__device__ __align__(16) __nv_bfloat16 g_qkv_h [(size_t)TBR * 3*EE], g_qkv_l [(size_t)TBR * 3*EE];
__device__ __align__(16) __nv_bfloat16 g_rp_h  [(size_t)RPAD * EE],  g_rp_l  [(size_t)RPAD * EE];
__device__ __align__(16) float g_bin [3*EE];
__device__ __align__(16) float g_bpos[EE];
__device__ __align__(16) float g_bout[EE];
__device__ __align__(16) float g_rw  [EE];
__device__ __align__(16) float g_rr  [EE];

// ---------------------------------------------------------------------------
// Portable PTX helpers (plain sm_103 target: NO tcgen05)
// ---------------------------------------------------------------------------
__device__ __forceinline__ uint32_t smem_u32(const void* p) {
    uint32_t a;
    asm("{ .reg .u64 t; cvta.to.shared.u64 t, %1; cvt.u32.u64 %0, t; }"
        : "=r"(a) : "l"(p));
    return a;
}
__device__ __forceinline__ void cp_async16(uint32_t dst, const void* src) {
    asm volatile("cp.async.cg.shared.global [%0], [%1], 16;"
                 :: "r"(dst), "l"(src) : "memory");
}
#define CP_COMMIT()  asm volatile("cp.async.commit_group;" ::: "memory")
#define CP_WAIT1()   asm volatile("cp.async.wait_group 1;" ::: "memory")
#define CP_WAIT0()   asm volatile("cp.async.wait_group 0;" ::: "memory")

#define LDSM4(r, a) asm volatile( \
    "ldmatrix.sync.aligned.m8n8.x4.shared.b16 {%0,%1,%2,%3}, [%4];" \
    : "=r"((r)[0]), "=r"((r)[1]), "=r"((r)[2]), "=r"((r)[3]) : "r"(a))

#define LDSM2(r, a) asm volatile( \
    "ldmatrix.sync.aligned.m8n8.x2.shared.b16 {%0,%1}, [%2];" \
    : "=r"((r)[0]), "=r"((r)[1]) : "r"(a))

// transposed: for B operand where k runs along smem ROWS (PV's V tile)
#define LDSM2T(r, a) asm volatile( \
    "ldmatrix.sync.aligned.m8n8.x2.trans.shared.b16 {%0,%1}, [%2];" \
    : "=r"((r)[0]), "=r"((r)[1]) : "r"(a))

#define MMA_BF16(c, a, b) asm volatile( \
    "mma.sync.aligned.m16n8k16.row.col.f32.bf16.bf16.f32 " \
    "{%0,%1,%2,%3}, {%4,%5,%6,%7}, {%8,%9}, {%0,%1,%2,%3};" \
    : "+f"((c)[0]), "+f"((c)[1]), "+f"((c)[2]), "+f"((c)[3]) \
    : "r"((a)[0]), "r"((a)[1]), "r"((a)[2]), "r"((a)[3]), \
      "r"((b)[0]), "r"((b)[1]))

// ---------------------------------------------------------------------------
// Kernel 1: hypernetwork matvec. W segments -> bf16 hi/lo; rest -> fp32.
// ---------------------------------------------------------------------------
#define SEG0 (3*EE*EE)
#define SEG1 (SEG0 + EE*EE)
#define SEG2 (SEG1 + EE*EE)
#define SEG3 (SEG2 + 3*EE)
#define SEG4 (SEG3 + EE)
#define SEG5 (SEG4 + EE)
#define SEG6 (SEG5 + EE)
#define SEG7 (SEG6 + EE)     // total = 5,250,048 = 20508*256

__global__ void hypernet_kernel(const float* __restrict__ w_in,
                                const float* __restrict__ w_pos,
                                const float* __restrict__ w_out,
                                const float* __restrict__ b_in,
                                const float* __restrict__ b_pos,
                                const float* __restrict__ b_out,
                                const float* __restrict__ rwb,
                                const float* __restrict__ rrb,
                                const float* __restrict__ fac)
{
    __shared__ float fs[8];
    if (threadIdx.x < 8) fs[threadIdx.x] = fac[threadIdx.x];
    __syncthreads();

    int idx = blockIdx.x * blockDim.x + threadIdx.x;
    if (idx >= SEG7) return;

    const float* src; int li;
    if      (idx < SEG0) { src = w_in;  li = idx;        }
    else if (idx < SEG1) { src = w_pos; li = idx - SEG0; }
    else if (idx < SEG2) { src = w_out; li = idx - SEG1; }
    else if (idx < SEG3) { src = b_in;  li = idx - SEG2; }
    else if (idx < SEG4) { src = b_pos; li = idx - SEG3; }
    else if (idx < SEG5) { src = b_out; li = idx - SEG4; }
    else if (idx < SEG6) { src = rwb;   li = idx - SEG5; }
    else                 { src = rrb;   li = idx - SEG6; }

    const float4* s4 = reinterpret_cast<const float4*>(src) + (size_t)li * 2;
    float4 a = s4[0];
    float4 b = s4[1];
    float w = a.x*fs[0] + a.y*fs[1] + a.z*fs[2] + a.w*fs[3]
            + b.x*fs[4] + b.y*fs[5] + b.z*fs[6] + b.w*fs[7];

    if (idx < SEG2) {
        __nv_bfloat16 h = __float2bfloat16(w);
        __nv_bfloat16 l = __float2bfloat16(w - __bfloat162float(h));
        if (idx < SEG0)      { g_Win_h [li] = h; g_Win_l [li] = l; }
        else if (idx < SEG1) { g_Wpos_h[li] = h; g_Wpos_l[li] = l; }
        else                 { g_Wout_h[li] = h; g_Wout_l[li] = l; }
    } else {
        float* dst;
        if      (idx < SEG3) dst = g_bin;
        else if (idx < SEG4) dst = g_bpos;
        else if (idx < SEG5) dst = g_bout;
        else if (idx < SEG6) dst = g_rw;
        else                 dst = g_rr;
        dst[li] = w;
    }
}

// ---------------------------------------------------------------------------
// Kernel 1b: split input / pos into bf16 hi/lo (pos padded to 4096 rows)
// ---------------------------------------------------------------------------
#define NIN4  (TBR * EE / 4)          // 524288
#define NPOS4 ((size_t)RPAD * EE / 4) // 1048576
#define NCONV_BLOCKS 6144             // (NIN4+NPOS4)/256

__global__ void convert_kernel(const float* __restrict__ input,
                               const float* __restrict__ pos)
{
    int idx = blockIdx.x * blockDim.x + threadIdx.x;   // float4 index
    float4 v;
    __nv_bfloat16 *dh, *dl;
    size_t o;
    if (idx < NIN4) {
        v = reinterpret_cast<const float4*>(input)[idx];
        dh = g_in_h; dl = g_in_l; o = (size_t)idx * 4;
    } else {
        size_t j = (size_t)idx - NIN4;
        if (j * 4 < (size_t)RBR * EE)
            v = reinterpret_cast<const float4*>(pos)[j];
        else
            v = make_float4(0.f, 0.f, 0.f, 0.f);
        dh = g_pos_h; dl = g_pos_l; o = j * 4;
    }
    __nv_bfloat16 h0 = __float2bfloat16(v.x), h1 = __float2bfloat16(v.y);
    __nv_bfloat16 h2 = __float2bfloat16(v.z), h3 = __float2bfloat16(v.w);
    __nv_bfloat162 hh0; hh0.x = h0; hh0.y = h1;
    __nv_bfloat162 hh1; hh1.x = h2; hh1.y = h3;
    __nv_bfloat162 ll0, ll1;
    ll0.x = __float2bfloat16(v.x - __bfloat162float(h0));
    ll0.y = __float2bfloat16(v.y - __bfloat162float(h1));
    ll1.x = __float2bfloat16(v.z - __bfloat162float(h2));
    ll1.y = __float2bfloat16(v.w - __bfloat162float(h3));
    *reinterpret_cast<__nv_bfloat162*>(&dh[o])     = hh0;
    *reinterpret_cast<__nv_bfloat162*>(&dh[o + 2]) = hh1;
    *reinterpret_cast<__nv_bfloat162*>(&dl[o])     = ll0;
    *reinterpret_cast<__nv_bfloat162*>(&dl[o + 2]) = ll1;
}

// ---------------------------------------------------------------------------
// Kernel 2: HMMA bf16x3 GEMM (NT): C[m][n] = bias[n] + sum_k A[m][k]*B[n][k]
//   which==0: A=input(split) B=Win  -> g_qkv_h/l (bf16 hi/lo, ldc=3072)
//   which==1: A=pos(split)   B=Wpos -> g_rp_h/l  (bf16 hi/lo, ldc=1024)
//   which==2: A=ao(split)    B=Wout -> Cext      (fp32,       ldc=1024)
// ---------------------------------------------------------------------------
#define BK 32
#define PITCH 80                 // bytes per smem row: 64 data + 16 pad
#define ARR   (128 * PITCH)      // 10240 bytes per tile array
#define STAGE (4 * ARR)          // Ah | Al | Bh | Bl
#define GEMM_SMEM (2 * STAGE)    // 81920

__global__ __launch_bounds__(256, 1)
void hmma_gemm(float* __restrict__ Cext, int which)
{
    const __nv_bfloat16 *Ah, *Al, *Bh, *Bl;
    const float* bias; int ldc;
    __nv_bfloat16 *Ch = nullptr, *Cl = nullptr;
    float* C = nullptr;
    if (which == 0)      { Ah = g_in_h;  Al = g_in_l;  Bh = g_Win_h;  Bl = g_Win_l;
                           bias = g_bin;  Ch = g_qkv_h; Cl = g_qkv_l; ldc = 3*EE; }
    else if (which == 1) { Ah = g_pos_h; Al = g_pos_l; Bh = g_Wpos_h; Bl = g_Wpos_l;
                           bias = g_bpos; Ch = g_rp_h;  Cl = g_rp_l;  ldc = EE; }
    else                 { Ah = g_ao_h;  Al = g_ao_l;  Bh = g_Wout_h; Bl = g_Wout_l;
                           bias = g_bout; C = Cext;  ldc = EE; }

    extern __shared__ char smem[];
    const uint32_t sb = smem_u32(smem);

    const int tid  = threadIdx.x;
    const int lane = tid & 31;
    const int wid  = tid >> 5;
    const int wr   = wid >> 1;          // 0..3  (m)
    const int wc   = wid & 1;           // 0..1  (n)
    const int m0   = blockIdx.y * 128;
    const int n0   = blockIdx.x * 128;

    auto load_chunk = [&](int c, int s) {
        const int kc = c * BK;
        #pragma unroll
        for (int it = 0; it < 8; it++) {
            int f   = tid + it * 256;        // 0..2047
            int arr = f >> 9;                // 0..3
            int rem = f & 511;
            int row = rem >> 2;              // 0..127
            int ch  = rem & 3;               // 16B chunk in row
            uint32_t dst = sb + s * STAGE + arr * ARR + row * PITCH + ch * 16;
            const __nv_bfloat16* gp;
            if      (arr == 0) gp = Ah + (size_t)(m0 + row) * EE + kc + ch * 8;
            else if (arr == 1) gp = Al + (size_t)(m0 + row) * EE + kc + ch * 8;
            else if (arr == 2) gp = Bh + (size_t)(n0 + row) * EE + kc + ch * 8;
            else               gp = Bl + (size_t)(n0 + row) * EE + kc + ch * 8;
            cp_async16(dst, gp);
        }
        CP_COMMIT();
    };

    float acc[2][8][4];
    #pragma unroll
    for (int mi = 0; mi < 2; mi++)
        #pragma unroll
        for (int ni = 0; ni < 8; ni++)
            #pragma unroll
            for (int q = 0; q < 4; q++) acc[mi][ni][q] = 0.f;

    load_chunk(0, 0);

    for (int c = 0; c < 32; c++) {
        const int s = c & 1;
        if (c + 1 < 32) { load_chunk(c + 1, s ^ 1); CP_WAIT1(); }
        else            { CP_WAIT0(); }
        __syncthreads();

        const uint32_t aH = sb + s * STAGE;
        const uint32_t aL = aH + ARR;
        const uint32_t bH = aH + 2 * ARR;
        const uint32_t bL = aH + 3 * ARR;
        const int l4 = lane & 15;

        #pragma unroll
        for (int kk = 0; kk < 2; kk++) {
            const int kb = kk * 32;

            uint32_t AH[2][4], AL[2][4];
            #pragma unroll
            for (int mi = 0; mi < 2; mi++) {
                uint32_t ro = (wr * 32 + mi * 16 + l4) * PITCH + kb + (lane >> 4) * 16;
                LDSM4(AH[mi], aH + ro);
                LDSM4(AL[mi], aL + ro);
            }
            uint32_t BH[8][2], BL[8][2];
            #pragma unroll
            for (int ni = 0; ni < 8; ni++) {
                uint32_t ro = (wc * 64 + ni * 8 + (l4 & 7)) * PITCH
                            + kb + ((l4 >> 3) & 1) * 16;
                LDSM2(BH[ni], bH + ro);
                LDSM2(BL[ni], bL + ro);
            }
            #pragma unroll
            for (int mi = 0; mi < 2; mi++)
                #pragma unroll
                for (int ni = 0; ni < 8; ni++) {
                    MMA_BF16(acc[mi][ni], AH[mi], BH[ni]);
                    MMA_BF16(acc[mi][ni], AH[mi], BL[ni]);
                    MMA_BF16(acc[mi][ni], AL[mi], BH[ni]);
                }
        }
        __syncthreads();
    }

    // ---- epilogue ----
    #pragma unroll
    for (int mi = 0; mi < 2; mi++) {
        #pragma unroll
        for (int r2 = 0; r2 < 2; r2++) {
            int grow = m0 + wr * 32 + mi * 16 + (lane >> 2) + r2 * 8;
            #pragma unroll
            for (int ni = 0; ni < 8; ni++) {
                int gcol = n0 + wc * 64 + ni * 8 + (lane & 3) * 2;
                float2 bv = *reinterpret_cast<const float2*>(&bias[gcol]);
                float ox = acc[mi][ni][r2 * 2 + 0] + bv.x;
                float oy = acc[mi][ni][r2 * 2 + 1] + bv.y;
                if (which == 2) {
                    *reinterpret_cast<float2*>(&C[(size_t)grow * ldc + gcol]) =
                        make_float2(ox, oy);
                } else {
                    __nv_bfloat16 hx = __float2bfloat16(ox);
                    __nv_bfloat16 hy = __float2bfloat16(oy);
                    __nv_bfloat162 hv; hv.x = hx; hv.y = hy;
                    __nv_bfloat162 lv;
                    lv.x = __float2bfloat16(ox - __bfloat162float(hx));
                    lv.y = __float2bfloat16(oy - __bfloat162float(hy));
                    *reinterpret_cast<__nv_bfloat162*>(&Ch[(size_t)grow * ldc + gcol]) = hv;
                    *reinterpret_cast<__nv_bfloat162*>(&Cl[(size_t)grow * ldc + gcol]) = lv;
                }
            }
        }
    }
}

// ---------------------------------------------------------------------------
// Kernel 3: MMA-based fused relative-position flash attention.
// Block = (64 q-rows, head, batch); 256 threads / 8 warps.
// Per 64-col tile jt:
//   AC  [64x64]  = (q+rw) . k           (mma, 3 hi/lo products)
//   BDm [64x128] = (q+rr) . rband       (mma in band coords, 3 products)
//   softmax on S[i][j] = AC[i][j] + BDm[i][j-i+63]  (scalar gather from smem)
//   O  += P . V                         (mma, 3 products, online rescale)
// Warp layout S-phase: band=wid>>1 owns rows band*16..+15; half=wid&1 splits
// the 192 output columns (64 AC + 128 BDm) into 96+96.
// PV: band rows, half = 32-wide d-half; accum in fragments across jt.
// ---------------------------------------------------------------------------
#define APB 144                        // bf16 tile row pitch (64*2 + 16 pad)
#define OFF_QWH 0
#define OFF_QWL (OFF_QWH + 64*APB)     //   9216
#define OFF_QRH (OFF_QWL + 64*APB)     //  18432
#define OFF_QRL (OFF_QRH + 64*APB)     //  27648
#define OFF_KH  (OFF_QRL + 64*APB)     //  36864
#define OFF_KL  (OFF_KH  + 64*APB)     //  46080
#define OFF_VH  (OFF_KL  + 64*APB)     //  55296
#define OFF_VL  (OFF_VH  + 64*APB)     //  64512
#define OFF_RBH (OFF_VL  + 64*APB)     //  73728
#define OFF_RBL (OFF_RBH + 128*APB)    //  92160
#define OFF_PH  (OFF_RBL + 128*APB)    // 110592
#define OFF_PL  (OFF_PH  + 64*APB)     // 119808
#define OFF_ACS (OFF_PL  + 64*APB)     // 129024  float[64][72]
#define OFF_BDS (OFF_ACS + 64*72*4)    // 147456  float[64][132]
#define OFF_ROW (OFF_BDS + 64*132*4)   // 181248  corr[64] + inv[64]
#define ATT2_SMEM (OFF_ROW + 512)      // 181760

__global__ __launch_bounds__(256, 1)
void attn_mma()
{
    extern __shared__ char smc[];
    const uint32_t sb = smem_u32(smc);
    float* ACS  = reinterpret_cast<float*>(smc + OFF_ACS);
    float* BDS  = reinterpret_cast<float*>(smc + OFF_BDS);
    float* rowc = reinterpret_cast<float*>(smc + OFF_ROW);        // corr[64]
    float* rowi = reinterpret_cast<float*>(smc + OFF_ROW + 256);  // 1/l [64]

    const int tid  = threadIdx.x;
    const int lane = tid & 31;
    const int wid  = tid >> 5;
    const int tx   = tid & 15;
    const int ty   = tid >> 4;
    const int band = wid >> 1;        // 0..3: 16-row band
    const int half = wid & 1;
    const int m0w  = band * 16;
    const int l4   = lane & 15;
    const int it   = blockIdx.x;
    const int h    = blockIdx.y;
    const int b    = blockIdx.z;
    const int i0   = it * 64;
    const int hc   = h * DD;

    // ---- build qw = q+rw, qr = q+rr as bf16 hi/lo in smem (once) ----
    #pragma unroll
    for (int rep = 0; rep < 2; rep++) {
        int f   = tid + rep * 256;        // 0..511
        int row = f >> 3;                 // 0..63
        int ch  = f & 7;                  // 16B chunk (8 bf16)
        size_t gq = ((size_t)(i0 + row) * BB + b) * (3 * EE) + hc + ch * 8;
        uint4 qh4 = *reinterpret_cast<const uint4*>(g_qkv_h + gq);
        uint4 ql4 = *reinterpret_cast<const uint4*>(g_qkv_l + gq);
        const __nv_bfloat16* qhp = reinterpret_cast<const __nv_bfloat16*>(&qh4);
        const __nv_bfloat16* qlp = reinterpret_cast<const __nv_bfloat16*>(&ql4);
        float4 rw0 = *reinterpret_cast<const float4*>(&g_rw[hc + ch * 8]);
        float4 rw1 = *reinterpret_cast<const float4*>(&g_rw[hc + ch * 8 + 4]);
        float4 rr0 = *reinterpret_cast<const float4*>(&g_rr[hc + ch * 8]);
        float4 rr1 = *reinterpret_cast<const float4*>(&g_rr[hc + ch * 8 + 4]);
        float rwv[8] = {rw0.x, rw0.y, rw0.z, rw0.w, rw1.x, rw1.y, rw1.z, rw1.w};
        float rrv[8] = {rr0.x, rr0.y, rr0.z, rr0.w, rr1.x, rr1.y, rr1.z, rr1.w};
        uint4 owh, owl, orh, orl;
        __nv_bfloat16* pwh = reinterpret_cast<__nv_bfloat16*>(&owh);
        __nv_bfloat16* pwl = reinterpret_cast<__nv_bfloat16*>(&owl);
        __nv_bfloat16* prh = reinterpret_cast<__nv_bfloat16*>(&orh);
        __nv_bfloat16* prl = reinterpret_cast<__nv_bfloat16*>(&orl);
        #pragma unroll
        for (int e = 0; e < 8; e++) {
            float q  = __bfloat162float(qhp[e]) + __bfloat162float(qlp[e]);
            float aw = q + rwv[e];
            float ar = q + rrv[e];
            __nv_bfloat16 hw = __float2bfloat16(aw);
            __nv_bfloat16 hr = __float2bfloat16(ar);
            pwh[e] = hw; pwl[e] = __float2bfloat16(aw - __bfloat162float(hw));
            prh[e] = hr; prl[e] = __float2bfloat16(ar - __bfloat162float(hr));
        }
        uint32_t so = row * APB + ch * 16;
        *reinterpret_cast<uint4*>(smc + OFF_QWH + so) = owh;
        *reinterpret_cast<uint4*>(smc + OFF_QWL + so) = owl;
        *reinterpret_cast<uint4*>(smc + OFF_QRH + so) = orh;
        *reinterpret_cast<uint4*>(smc + OFF_QRL + so) = orl;
    }

    float m_i[4], l_i[4];
    #pragma unroll
    for (int a = 0; a < 4; a++) { m_i[a] = -1e30f; l_i[a] = 0.f; }
    float accO[4][4];
    #pragma unroll
    for (int ni = 0; ni < 4; ni++)
        #pragma unroll
        for (int q = 0; q < 4; q++) accO[ni][q] = 0.f;

    for (int jt = 0; jt < 16; jt++) {
        const int j0 = jt * 64;
        const int rbase = 1023 + j0 - i0 - 63;
        __syncthreads();   // prev PV reads of k/v/p done; q tiles ready (jt=0)

        // ---- cp.async: k,v (64 rows) and rband (128 rows), hi+lo ----
        #pragma unroll
        for (int rep = 0; rep < 16; rep++) {
            int f = tid + rep * 256;              // 0..4095
            if (f < 2048) {
                int arr = f >> 9;                 // 0:kh 1:kl 2:vh 3:vl
                int rem = f & 511;
                int row = rem >> 3, ch = rem & 7;
                size_t base = ((size_t)(j0 + row) * BB + b) * (3 * EE) + hc + ch * 8;
                const __nv_bfloat16* gp;
                uint32_t off;
                if      (arr == 0) { gp = g_qkv_h + base + EE;     off = OFF_KH; }
                else if (arr == 1) { gp = g_qkv_l + base + EE;     off = OFF_KL; }
                else if (arr == 2) { gp = g_qkv_h + base + 2 * EE; off = OFF_VH; }
                else               { gp = g_qkv_l + base + 2 * EE; off = OFF_VL; }
                cp_async16(sb + off + row * APB + ch * 16, gp);
            } else {
                int f2  = f - 2048;
                int arr = f2 >> 10;               // 0:rbh 1:rbl
                int rem = f2 & 1023;
                int row = rem >> 3, ch = rem & 7;
                size_t base = ((size_t)(rbase + row) * BB + b) * EE + hc + ch * 8;
                const __nv_bfloat16* gp = (arr == 0 ? g_rp_h : g_rp_l) + base;
                uint32_t off = (arr == 0 ? OFF_RBH : OFF_RBL);
                cp_async16(sb + off + row * APB + ch * 16, gp);
            }
        }
        CP_COMMIT();
        CP_WAIT0();
        __syncthreads();

        // ---- S phase: AC + BDm via mma ----
        float acc[12][4];
        #pragma unroll
        for (int t = 0; t < 12; t++)
            #pragma unroll
            for (int q = 0; q < 4; q++) acc[t][q] = 0.f;

        #pragma unroll
        for (int ks = 0; ks < 4; ks++) {
            const int kb = ks * 32;
            uint32_t ro = (m0w + l4) * APB + kb + (lane >> 4) * 16;
            uint32_t ARH[4], ARL[4];
            LDSM4(ARH, sb + OFF_QRH + ro);
            LDSM4(ARL, sb + OFF_QRL + ro);
            if (half == 0) {
                uint32_t AWH[4], AWL[4];
                LDSM4(AWH, sb + OFF_QWH + ro);
                LDSM4(AWL, sb + OFF_QWL + ro);
                #pragma unroll
                for (int ni = 0; ni < 8; ni++) {  // AC tiles
                    uint32_t bo = (ni * 8 + (l4 & 7)) * APB + kb + ((l4 >> 3) & 1) * 16;
                    uint32_t BH[2], BL[2];
                    LDSM2(BH, sb + OFF_KH + bo);
                    LDSM2(BL, sb + OFF_KL + bo);
                    MMA_BF16(acc[ni], AWH, BH);
                    MMA_BF16(acc[ni], AWH, BL);
                    MMA_BF16(acc[ni], AWL, BH);
                }
                #pragma unroll
                for (int t = 0; t < 4; t++) {     // BDm tiles u 0..31
                    uint32_t bo = (t * 8 + (l4 & 7)) * APB + kb + ((l4 >> 3) & 1) * 16;
                    uint32_t BH[2], BL[2];
                    LDSM2(BH, sb + OFF_RBH + bo);
                    LDSM2(BL, sb + OFF_RBL + bo);
                    MMA_BF16(acc[8 + t], ARH, BH);
                    MMA_BF16(acc[8 + t], ARH, BL);
                    MMA_BF16(acc[8 + t], ARL, BH);
                }
            } else {
                #pragma unroll
                for (int t = 0; t < 12; t++) {    // BDm tiles u 32..127
                    uint32_t bo = ((4 + t) * 8 + (l4 & 7)) * APB + kb + ((l4 >> 3) & 1) * 16;
                    uint32_t BH[2], BL[2];
                    LDSM2(BH, sb + OFF_RBH + bo);
                    LDSM2(BL, sb + OFF_RBL + bo);
                    MMA_BF16(acc[t], ARH, BH);
                    MMA_BF16(acc[t], ARH, BL);
                    MMA_BF16(acc[t], ARL, BH);
                }
            }
        }

        // ---- store S fragments to smem ----
        {
            const int r0 = m0w + (lane >> 2);
            const int cc = (lane & 3) * 2;
            if (half == 0) {
                #pragma unroll
                for (int ni = 0; ni < 8; ni++) {
                    *reinterpret_cast<float2*>(&ACS[r0 * 72 + ni * 8 + cc]) =
                        make_float2(acc[ni][0], acc[ni][1]);
                    *reinterpret_cast<float2*>(&ACS[(r0 + 8) * 72 + ni * 8 + cc]) =
                        make_float2(acc[ni][2], acc[ni][3]);
                }
                #pragma unroll
                for (int t = 0; t < 4; t++) {
                    *reinterpret_cast<float2*>(&BDS[r0 * 132 + t * 8 + cc]) =
                        make_float2(acc[8 + t][0], acc[8 + t][1]);
                    *reinterpret_cast<float2*>(&BDS[(r0 + 8) * 132 + t * 8 + cc]) =
                        make_float2(acc[8 + t][2], acc[8 + t][3]);
                }
            } else {
                #pragma unroll
                for (int t = 0; t < 12; t++) {
                    *reinterpret_cast<float2*>(&BDS[r0 * 132 + (4 + t) * 8 + cc]) =
                        make_float2(acc[t][0], acc[t][1]);
                    *reinterpret_cast<float2*>(&BDS[(r0 + 8) * 132 + (4 + t) * 8 + cc]) =
                        make_float2(acc[t][2], acc[t][3]);
                }
            }
        }
        __syncthreads();

        // ---- softmax (thread (tx,ty) owns rows ty*4+a, cols tx*4..+3) ----
        #pragma unroll
        for (int a = 0; a < 4; a++) {
            const int i = ty * 4 + a;
            float s[4];
            float mx = -1e30f;
            #pragma unroll
            for (int c = 0; c < 4; c++) {
                const int j = tx * 4 + c;
                float v = ACS[i * 72 + j] + BDS[i * 132 + (j - i + 63)];
                s[c] = v * 0.125f;
                mx = fmaxf(mx, s[c]);
            }
            #pragma unroll
            for (int off = 8; off > 0; off >>= 1)
                mx = fmaxf(mx, __shfl_xor_sync(0xffffffffu, mx, off));
            float mnew = fmaxf(m_i[a], mx);
            float corr = __expf(m_i[a] - mnew);
            float p[4]; float psum = 0.f;
            #pragma unroll
            for (int c = 0; c < 4; c++) {
                p[c] = __expf(s[c] - mnew);
                psum += p[c];
            }
            #pragma unroll
            for (int off = 8; off > 0; off >>= 1)
                psum += __shfl_xor_sync(0xffffffffu, psum, off);
            l_i[a] = l_i[a] * corr + psum;
            m_i[a] = mnew;
            if (tx == 0) rowc[i] = corr;
            // write p hi/lo bf16 (4 values = 8B each)
            __nv_bfloat162 ph0, ph1, pl0, pl1;
            __nv_bfloat16 h0 = __float2bfloat16(p[0]);
            __nv_bfloat16 h1 = __float2bfloat16(p[1]);
            __nv_bfloat16 h2 = __float2bfloat16(p[2]);
            __nv_bfloat16 h3 = __float2bfloat16(p[3]);
            ph0.x = h0; ph0.y = h1; ph1.x = h2; ph1.y = h3;
            pl0.x = __float2bfloat16(p[0] - __bfloat162float(h0));
            pl0.y = __float2bfloat16(p[1] - __bfloat162float(h1));
            pl1.x = __float2bfloat16(p[2] - __bfloat162float(h2));
            pl1.y = __float2bfloat16(p[3] - __bfloat162float(h3));
            uint32_t po = i * APB + tx * 8;
            *reinterpret_cast<__nv_bfloat162*>(smc + OFF_PH + po)     = ph0;
            *reinterpret_cast<__nv_bfloat162*>(smc + OFF_PH + po + 4) = ph1;
            *reinterpret_cast<__nv_bfloat162*>(smc + OFF_PL + po)     = pl0;
            *reinterpret_cast<__nv_bfloat162*>(smc + OFF_PL + po + 4) = pl1;
        }
        __syncthreads();

        // ---- PV: rescale O frags, then O += P.V ----
        {
            float c0 = rowc[m0w + (lane >> 2)];
            float c1 = rowc[m0w + 8 + (lane >> 2)];
            #pragma unroll
            for (int ni = 0; ni < 4; ni++) {
                accO[ni][0] *= c0; accO[ni][1] *= c0;
                accO[ni][2] *= c1; accO[ni][3] *= c1;
            }
            #pragma unroll
            for (int ks = 0; ks < 4; ks++) {      // k = 16 j-values
                const int kb = ks * 32;
                uint32_t ro = (m0w + l4) * APB + kb + (lane >> 4) * 16;
                uint32_t PH[4], PL[4];
                LDSM4(PH, sb + OFF_PH + ro);
                LDSM4(PL, sb + OFF_PL + ro);
                #pragma unroll
                for (int ni = 0; ni < 4; ni++) {  // 8 d-cols each
                    int d0 = half * 32 + ni * 8;
                    uint32_t vo = (ks * 16 + l4) * APB + d0 * 2;
                    uint32_t BH[2], BL[2];
                    LDSM2T(BH, sb + OFF_VH + vo);
                    LDSM2T(BL, sb + OFF_VL + vo);
                    MMA_BF16(accO[ni], PH, BH);
                    MMA_BF16(accO[ni], PH, BL);
                    MMA_BF16(accO[ni], PL, BH);
                }
            }
        }
        // loop-start __syncthreads protects k/v/p reuse
    }

    // ---- write 1/l, then O -> g_ao hi/lo ----
    #pragma unroll
    for (int a = 0; a < 4; a++)
        if (tx == 0) rowi[ty * 4 + a] = 1.0f / l_i[a];
    __syncthreads();

    {
        float i0v = rowi[m0w + (lane >> 2)];
        float i1v = rowi[m0w + 8 + (lane >> 2)];
        int r0 = i0 + m0w + (lane >> 2);
        #pragma unroll
        for (int ni = 0; ni < 4; ni++) {
            int dcol = hc + half * 32 + ni * 8 + (lane & 3) * 2;
            float o00 = accO[ni][0] * i0v, o01 = accO[ni][1] * i0v;
            float o10 = accO[ni][2] * i1v, o11 = accO[ni][3] * i1v;
            size_t b0 = ((size_t)r0 * BB + b) * EE + dcol;
            size_t b1 = ((size_t)(r0 + 8) * BB + b) * EE + dcol;
            __nv_bfloat16 h00 = __float2bfloat16(o00), h01 = __float2bfloat16(o01);
            __nv_bfloat16 h10 = __float2bfloat16(o10), h11 = __float2bfloat16(o11);
            __nv_bfloat162 hv0; hv0.x = h00; hv0.y = h01;
            __nv_bfloat162 hv1; hv1.x = h10; hv1.y = h11;
            __nv_bfloat162 lv0, lv1;
            lv0.x = __float2bfloat16(o00 - __bfloat162float(h00));
            lv0.y = __float2bfloat16(o01 - __bfloat162float(h01));
            lv1.x = __float2bfloat16(o10 - __bfloat162float(h10));
            lv1.y = __float2bfloat16(o11 - __bfloat162float(h11));
            *reinterpret_cast<__nv_bfloat162*>(&g_ao_h[b0]) = hv0;
            *reinterpret_cast<__nv_bfloat162*>(&g_ao_l[b0]) = lv0;
            *reinterpret_cast<__nv_bfloat162*>(&g_ao_h[b1]) = hv1;
            *reinterpret_cast<__nv_bfloat162*>(&g_ao_l[b1]) = lv1;
        }
    }
}

// ---------------------------------------------------------------------------
// Host launcher (graph-capturable: kernel launches only)
// ---------------------------------------------------------------------------
extern "C" void kernel_launch(void* const* d_in, const int* in_sizes, int n_in,
                              void* d_out, int out_size)
{
    const float* input  = (const float*)d_in[0];
    const float* pos    = (const float*)d_in[1];
    const float* factor = (const float*)d_in[2];
    const float* w_in   = (const float*)d_in[3];
    const float* w_pos  = (const float*)d_in[4];
    const float* w_out  = (const float*)d_in[5];
    const float* b_in   = (const float*)d_in[6];
    const float* b_pos  = (const float*)d_in[7];
    const float* b_out  = (const float*)d_in[8];
    const float* rwb    = (const float*)d_in[9];
    const float* rrb    = (const float*)d_in[10];
    float* out = (float*)d_out;

    cudaFuncSetAttribute(attn_mma,
                         cudaFuncAttributeMaxDynamicSharedMemorySize,
                         ATT2_SMEM);
    cudaFuncSetAttribute(hmma_gemm,
                         cudaFuncAttributeMaxDynamicSharedMemorySize,
                         GEMM_SMEM);

    // 1) hypernetwork (W -> bf16 hi/lo) + input/pos split
    hypernet_kernel<<<SEG7 / 256, 256>>>(w_in, w_pos, w_out, b_in, b_pos, b_out,
                                         rwb, rrb, factor);
    convert_kernel<<<NCONV_BLOCKS, 256>>>(input, pos);

    // 2) qkv = input @ W_in^T + b_in   : [2048, 3072] (bf16 hi/lo out)
    hmma_gemm<<<dim3(3072 / 128, TBR / 128), 256, GEMM_SMEM>>>(nullptr, 0);

    // 3) r = pos @ W_pos^T + b_pos     : [4096(pad), 1024] (bf16 hi/lo out)
    hmma_gemm<<<dim3(EE / 128, RPAD / 128), 256, GEMM_SMEM>>>(nullptr, 1);

    // 4) fused relative attention (mma.sync) -> ao (bf16 hi/lo)
    attn_mma<<<dim3(TT / 64, HH, BB), 256, ATT2_SMEM>>>();

    // 5) out = ao @ W_out^T + b_out    : [2048, 1024] -> d_out (fp32)
    hmma_gemm<<<dim3(EE / 128, TBR / 128), 256, GEMM_SMEM>>>(out, 2);
}

// round 9
// speedup vs baseline: 2.7778x; 1.1620x over previous
#include <cuda_runtime.h>
#include <cuda_bf16.h>
#include <cstdint>

// ---------------------------------------------------------------------------
// Problem constants
// ---------------------------------------------------------------------------
#define TT 1024
#define BB 2
#define EE 1024
#define HH 16
#define DD 64
#define RR 2047              // 2T-1
#define TBR (TT*BB)          // 2048 rows of [E]
#define RBR (RR*BB)          // 4094 valid pos rows
#define RPAD 4096            // padded pos rows (multiple of 128)

// ---------------------------------------------------------------------------
// Device scratch (static; no runtime allocation)
// ---------------------------------------------------------------------------
__device__ __align__(16) __nv_bfloat16 g_Win_h [3*EE*EE], g_Win_l [3*EE*EE];
__device__ __align__(16) __nv_bfloat16 g_Wpos_h[EE*EE],   g_Wpos_l[EE*EE];
__device__ __align__(16) __nv_bfloat16 g_Wout_h[EE*EE],   g_Wout_l[EE*EE];
__device__ __align__(16) __nv_bfloat16 g_in_h  [TBR*EE],  g_in_l  [TBR*EE];
__device__ __align__(16) __nv_bfloat16 g_pos_h [(size_t)RPAD*EE], g_pos_l[(size_t)RPAD*EE];
__device__ __align__(16) __nv_bfloat16 g_ao_h  [TBR*EE],  g_ao_l  [TBR*EE];
__device__ __align__(16) __nv_bfloat16 g_qkv_h [(size_t)TBR * 3*EE], g_qkv_l [(size_t)TBR * 3*EE];
__device__ __align__(16) __nv_bfloat16 g_rp_h  [(size_t)RPAD * EE],  g_rp_l  [(size_t)RPAD * EE];
__device__ __align__(16) float g_bin [3*EE];
__device__ __align__(16) float g_bpos[EE];
__device__ __align__(16) float g_bout[EE];
__device__ __align__(16) float g_rw  [EE];
__device__ __align__(16) float g_rr  [EE];

// ---------------------------------------------------------------------------
// Portable PTX helpers (plain sm_103 target: NO tcgen05)
// ---------------------------------------------------------------------------
__device__ __forceinline__ uint32_t smem_u32(const void* p) {
    uint32_t a;
    asm("{ .reg .u64 t; cvta.to.shared.u64 t, %1; cvt.u32.u64 %0, t; }"
        : "=r"(a) : "l"(p));
    return a;
}
__device__ __forceinline__ void cp_async16(uint32_t dst, const void* src) {
    asm volatile("cp.async.cg.shared.global [%0], [%1], 16;"
                 :: "r"(dst), "l"(src) : "memory");
}
#define CP_COMMIT()  asm volatile("cp.async.commit_group;" ::: "memory")
#define CP_WAIT1()   asm volatile("cp.async.wait_group 1;" ::: "memory")
#define CP_WAIT0()   asm volatile("cp.async.wait_group 0;" ::: "memory")

#define LDSM4(r, a) asm volatile( \
    "ldmatrix.sync.aligned.m8n8.x4.shared.b16 {%0,%1,%2,%3}, [%4];" \
    : "=r"((r)[0]), "=r"((r)[1]), "=r"((r)[2]), "=r"((r)[3]) : "r"(a))

#define LDSM2(r, a) asm volatile( \
    "ldmatrix.sync.aligned.m8n8.x2.shared.b16 {%0,%1}, [%2];" \
    : "=r"((r)[0]), "=r"((r)[1]) : "r"(a))

#define LDSM2T(r, a) asm volatile( \
    "ldmatrix.sync.aligned.m8n8.x2.trans.shared.b16 {%0,%1}, [%2];" \
    : "=r"((r)[0]), "=r"((r)[1]) : "r"(a))

#define MMA_BF16(c, a, b) asm volatile( \
    "mma.sync.aligned.m16n8k16.row.col.f32.bf16.bf16.f32 " \
    "{%0,%1,%2,%3}, {%4,%5,%6,%7}, {%8,%9}, {%0,%1,%2,%3};" \
    : "+f"((c)[0]), "+f"((c)[1]), "+f"((c)[2]), "+f"((c)[3]) \
    : "r"((a)[0]), "r"((a)[1]), "r"((a)[2]), "r"((a)[3]), \
      "r"((b)[0]), "r"((b)[1]))

// ---------------------------------------------------------------------------
// Kernel 1: hypernetwork matvec. W segments -> bf16 hi/lo; rest -> fp32.
// ---------------------------------------------------------------------------
#define SEG0 (3*EE*EE)
#define SEG1 (SEG0 + EE*EE)
#define SEG2 (SEG1 + EE*EE)
#define SEG3 (SEG2 + 3*EE)
#define SEG4 (SEG3 + EE)
#define SEG5 (SEG4 + EE)
#define SEG6 (SEG5 + EE)
#define SEG7 (SEG6 + EE)     // total = 5,250,048 = 20508*256

__global__ void hypernet_kernel(const float* __restrict__ w_in,
                                const float* __restrict__ w_pos,
                                const float* __restrict__ w_out,
                                const float* __restrict__ b_in,
                                const float* __restrict__ b_pos,
                                const float* __restrict__ b_out,
                                const float* __restrict__ rwb,
                                const float* __restrict__ rrb,
                                const float* __restrict__ fac)
{
    __shared__ float fs[8];
    if (threadIdx.x < 8) fs[threadIdx.x] = fac[threadIdx.x];
    __syncthreads();

    int idx = blockIdx.x * blockDim.x + threadIdx.x;
    if (idx >= SEG7) return;

    const float* src; int li;
    if      (idx < SEG0) { src = w_in;  li = idx;        }
    else if (idx < SEG1) { src = w_pos; li = idx - SEG0; }
    else if (idx < SEG2) { src = w_out; li = idx - SEG1; }
    else if (idx < SEG3) { src = b_in;  li = idx - SEG2; }
    else if (idx < SEG4) { src = b_pos; li = idx - SEG3; }
    else if (idx < SEG5) { src = b_out; li = idx - SEG4; }
    else if (idx < SEG6) { src = rwb;   li = idx - SEG5; }
    else                 { src = rrb;   li = idx - SEG6; }

    const float4* s4 = reinterpret_cast<const float4*>(src) + (size_t)li * 2;
    float4 a = s4[0];
    float4 b = s4[1];
    float w = a.x*fs[0] + a.y*fs[1] + a.z*fs[2] + a.w*fs[3]
            + b.x*fs[4] + b.y*fs[5] + b.z*fs[6] + b.w*fs[7];

    if (idx < SEG2) {
        __nv_bfloat16 h = __float2bfloat16(w);
        __nv_bfloat16 l = __float2bfloat16(w - __bfloat162float(h));
        if (idx < SEG0)      { g_Win_h [li] = h; g_Win_l [li] = l; }
        else if (idx < SEG1) { g_Wpos_h[li] = h; g_Wpos_l[li] = l; }
        else                 { g_Wout_h[li] = h; g_Wout_l[li] = l; }
    } else {
        float* dst;
        if      (idx < SEG3) dst = g_bin;
        else if (idx < SEG4) dst = g_bpos;
        else if (idx < SEG5) dst = g_bout;
        else if (idx < SEG6) dst = g_rw;
        else                 dst = g_rr;
        dst[li] = w;
    }
}

// ---------------------------------------------------------------------------
// Kernel 1b: split input / pos into bf16 hi/lo (pos padded to 4096 rows)
// ---------------------------------------------------------------------------
#define NIN4  (TBR * EE / 4)          // 524288
#define NPOS4 ((size_t)RPAD * EE / 4) // 1048576
#define NCONV_BLOCKS 6144             // (NIN4+NPOS4)/256

__global__ void convert_kernel(const float* __restrict__ input,
                               const float* __restrict__ pos)
{
    int idx = blockIdx.x * blockDim.x + threadIdx.x;   // float4 index
    float4 v;
    __nv_bfloat16 *dh, *dl;
    size_t o;
    if (idx < NIN4) {
        v = reinterpret_cast<const float4*>(input)[idx];
        dh = g_in_h; dl = g_in_l; o = (size_t)idx * 4;
    } else {
        size_t j = (size_t)idx - NIN4;
        if (j * 4 < (size_t)RBR * EE)
            v = reinterpret_cast<const float4*>(pos)[j];
        else
            v = make_float4(0.f, 0.f, 0.f, 0.f);
        dh = g_pos_h; dl = g_pos_l; o = j * 4;
    }
    __nv_bfloat16 h0 = __float2bfloat16(v.x), h1 = __float2bfloat16(v.y);
    __nv_bfloat16 h2 = __float2bfloat16(v.z), h3 = __float2bfloat16(v.w);
    __nv_bfloat162 hh0; hh0.x = h0; hh0.y = h1;
    __nv_bfloat162 hh1; hh1.x = h2; hh1.y = h3;
    __nv_bfloat162 ll0, ll1;
    ll0.x = __float2bfloat16(v.x - __bfloat162float(h0));
    ll0.y = __float2bfloat16(v.y - __bfloat162float(h1));
    ll1.x = __float2bfloat16(v.z - __bfloat162float(h2));
    ll1.y = __float2bfloat16(v.w - __bfloat162float(h3));
    *reinterpret_cast<__nv_bfloat162*>(&dh[o])     = hh0;
    *reinterpret_cast<__nv_bfloat162*>(&dh[o + 2]) = hh1;
    *reinterpret_cast<__nv_bfloat162*>(&dl[o])     = ll0;
    *reinterpret_cast<__nv_bfloat162*>(&dl[o + 2]) = ll1;
}

// ---------------------------------------------------------------------------
// Kernel 2: HMMA bf16x3 GEMM (NT): C[m][n] = bias[n] + sum_k A[m][k]*B[n][k]
// launch_bounds(256,2): <=128 regs so 2 CTAs/SM (reg file bound before).
// B fragments loaded inline to keep live registers low.
// ---------------------------------------------------------------------------
#define BK 32
#define PITCH 80                 // bytes per smem row: 64 data + 16 pad
#define ARR   (128 * PITCH)      // 10240 bytes per tile array
#define STAGE (4 * ARR)          // Ah | Al | Bh | Bl
#define GEMM_SMEM (2 * STAGE)    // 81920

__global__ __launch_bounds__(256, 2)
void hmma_gemm(float* __restrict__ Cext, int which)
{
    const __nv_bfloat16 *Ah, *Al, *Bh, *Bl;
    const float* bias; int ldc;
    __nv_bfloat16 *Ch = nullptr, *Cl = nullptr;
    float* C = nullptr;
    if (which == 0)      { Ah = g_in_h;  Al = g_in_l;  Bh = g_Win_h;  Bl = g_Win_l;
                           bias = g_bin;  Ch = g_qkv_h; Cl = g_qkv_l; ldc = 3*EE; }
    else if (which == 1) { Ah = g_pos_h; Al = g_pos_l; Bh = g_Wpos_h; Bl = g_Wpos_l;
                           bias = g_bpos; Ch = g_rp_h;  Cl = g_rp_l;  ldc = EE; }
    else                 { Ah = g_ao_h;  Al = g_ao_l;  Bh = g_Wout_h; Bl = g_Wout_l;
                           bias = g_bout; C = Cext;  ldc = EE; }

    extern __shared__ char smem[];
    const uint32_t sb = smem_u32(smem);

    const int tid  = threadIdx.x;
    const int lane = tid & 31;
    const int wid  = tid >> 5;
    const int wr   = wid >> 1;          // 0..3  (m)
    const int wc   = wid & 1;           // 0..1  (n)
    const int m0   = blockIdx.y * 128;
    const int n0   = blockIdx.x * 128;

    auto load_chunk = [&](int c, int s) {
        const int kc = c * BK;
        #pragma unroll
        for (int it = 0; it < 8; it++) {
            int f   = tid + it * 256;        // 0..2047
            int arr = f >> 9;                // 0..3
            int rem = f & 511;
            int row = rem >> 2;              // 0..127
            int ch  = rem & 3;               // 16B chunk in row
            uint32_t dst = sb + s * STAGE + arr * ARR + row * PITCH + ch * 16;
            const __nv_bfloat16* gp;
            if      (arr == 0) gp = Ah + (size_t)(m0 + row) * EE + kc + ch * 8;
            else if (arr == 1) gp = Al + (size_t)(m0 + row) * EE + kc + ch * 8;
            else if (arr == 2) gp = Bh + (size_t)(n0 + row) * EE + kc + ch * 8;
            else               gp = Bl + (size_t)(n0 + row) * EE + kc + ch * 8;
            cp_async16(dst, gp);
        }
        CP_COMMIT();
    };

    float acc[2][8][4];
    #pragma unroll
    for (int mi = 0; mi < 2; mi++)
        #pragma unroll
        for (int ni = 0; ni < 8; ni++)
            #pragma unroll
            for (int q = 0; q < 4; q++) acc[mi][ni][q] = 0.f;

    load_chunk(0, 0);

    for (int c = 0; c < 32; c++) {
        const int s = c & 1;
        if (c + 1 < 32) { load_chunk(c + 1, s ^ 1); CP_WAIT1(); }
        else            { CP_WAIT0(); }
        __syncthreads();

        const uint32_t aH = sb + s * STAGE;
        const uint32_t aL = aH + ARR;
        const uint32_t bH = aH + 2 * ARR;
        const uint32_t bL = aH + 3 * ARR;
        const int l4 = lane & 15;

        #pragma unroll
        for (int kk = 0; kk < 2; kk++) {
            const int kb = kk * 32;

            uint32_t AH[2][4], AL[2][4];
            #pragma unroll
            for (int mi = 0; mi < 2; mi++) {
                uint32_t ro = (wr * 32 + mi * 16 + l4) * PITCH + kb + (lane >> 4) * 16;
                LDSM4(AH[mi], aH + ro);
                LDSM4(AL[mi], aL + ro);
            }
            #pragma unroll
            for (int ni = 0; ni < 8; ni++) {
                uint32_t ro = (wc * 64 + ni * 8 + (l4 & 7)) * PITCH
                            + kb + ((l4 >> 3) & 1) * 16;
                uint32_t BH[2], BL[2];
                LDSM2(BH, bH + ro);
                LDSM2(BL, bL + ro);
                #pragma unroll
                for (int mi = 0; mi < 2; mi++) {
                    MMA_BF16(acc[mi][ni], AH[mi], BH);
                    MMA_BF16(acc[mi][ni], AH[mi], BL);
                    MMA_BF16(acc[mi][ni], AL[mi], BH);
                }
            }
        }
        __syncthreads();
    }

    // ---- epilogue ----
    #pragma unroll
    for (int mi = 0; mi < 2; mi++) {
        #pragma unroll
        for (int r2 = 0; r2 < 2; r2++) {
            int grow = m0 + wr * 32 + mi * 16 + (lane >> 2) + r2 * 8;
            #pragma unroll
            for (int ni = 0; ni < 8; ni++) {
                int gcol = n0 + wc * 64 + ni * 8 + (lane & 3) * 2;
                float2 bv = *reinterpret_cast<const float2*>(&bias[gcol]);
                float ox = acc[mi][ni][r2 * 2 + 0] + bv.x;
                float oy = acc[mi][ni][r2 * 2 + 1] + bv.y;
                if (which == 2) {
                    *reinterpret_cast<float2*>(&C[(size_t)grow * ldc + gcol]) =
                        make_float2(ox, oy);
                } else {
                    __nv_bfloat16 hx = __float2bfloat16(ox);
                    __nv_bfloat16 hy = __float2bfloat16(oy);
                    __nv_bfloat162 hv; hv.x = hx; hv.y = hy;
                    __nv_bfloat162 lv;
                    lv.x = __float2bfloat16(ox - __bfloat162float(hx));
                    lv.y = __float2bfloat16(oy - __bfloat162float(hy));
                    *reinterpret_cast<__nv_bfloat162*>(&Ch[(size_t)grow * ldc + gcol]) = hv;
                    *reinterpret_cast<__nv_bfloat162*>(&Cl[(size_t)grow * ldc + gcol]) = lv;
                }
            }
        }
    }
}

// ---------------------------------------------------------------------------
// Kernel 3: MMA flash attention with BD band-tile skipping + pipelined loads.
// Band b (rows 16b..16b+15) only needs BD u-tiles [6-2b, 15-2b] (10 of 16):
//   for row i, gather index u = j-i+63 in [48-16b, 126-16b]  (proven subset).
// Warp split per band: half0 = 8 AC tiles + BD tile tb0; half1 = BD tb0+1..+9.
// Pipeline: k/rb single-buffered but re-filled for jt+1 right after S-phase
// (k/rb dead once S frags stored); v double-buffered (read late, in PV).
// cp.async for jt+1 overlaps softmax+PV of jt.
// ---------------------------------------------------------------------------
#define APB 144                        // bf16 tile row pitch (64*2 + 16 pad)
#define OFF_QWH 0
#define OFF_QWL (OFF_QWH + 64*APB)
#define OFF_QRH (OFF_QWL + 64*APB)
#define OFF_QRL (OFF_QRH + 64*APB)
#define OFF_KH  (OFF_QRL + 64*APB)
#define OFF_KL  (OFF_KH  + 64*APB)
#define OFF_V   (OFF_KL  + 64*APB)     // 2 stages x (VH | VL)
#define VSTG    (2 * 64 * APB)
#define OFF_RBH (OFF_V + 2*VSTG)
#define OFF_RBL (OFF_RBH + 128*APB)
#define OFF_PH  (OFF_RBL + 128*APB)
#define OFF_PL  (OFF_PH  + 64*APB)
#define OFF_ACS (OFF_PL  + 64*APB)     // float[64][72]
#define OFF_BDS (OFF_ACS + 64*72*4)    // float[64][132]
#define OFF_ROW (OFF_BDS + 64*132*4)   // corr[64] + inv[64]
#define ATT2_SMEM (OFF_ROW + 512)      // 200192

__global__ __launch_bounds__(256, 1)
void attn_mma()
{
    extern __shared__ char smc[];
    const uint32_t sb = smem_u32(smc);
    float* ACS  = reinterpret_cast<float*>(smc + OFF_ACS);
    float* BDS  = reinterpret_cast<float*>(smc + OFF_BDS);
    float* rowc = reinterpret_cast<float*>(smc + OFF_ROW);
    float* rowi = reinterpret_cast<float*>(smc + OFF_ROW + 256);

    const int tid  = threadIdx.x;
    const int lane = tid & 31;
    const int wid  = tid >> 5;
    const int tx   = tid & 15;
    const int ty   = tid >> 4;
    const int band = wid >> 1;        // 0..3: 16-row band
    const int half = wid & 1;
    const int m0w  = band * 16;
    const int tb0  = 6 - 2 * band;    // first live BD u-tile for this band
    const int l4   = lane & 15;
    const int it   = blockIdx.x;
    const int h    = blockIdx.y;
    const int b    = blockIdx.z;
    const int i0   = it * 64;
    const int hc   = h * DD;

    // ---- async loader for one jt: k (S-phase), rb (S-phase), v[vs] (PV) ----
    auto load_tiles = [&](int jt, int vs) {
        const int j0 = jt * 64;
        const int rbase = 1023 + j0 - i0 - 63;
        #pragma unroll
        for (int rep = 0; rep < 16; rep++) {
            int f = tid + rep * 256;              // 0..4095
            if (f < 1024) {                       // k hi/lo
                int arr = f >> 9;
                int rem = f & 511;
                int row = rem >> 3, ch = rem & 7;
                size_t base = ((size_t)(j0 + row) * BB + b) * (3 * EE) + hc + EE + ch * 8;
                const __nv_bfloat16* gp = (arr == 0 ? g_qkv_h : g_qkv_l) + base;
                uint32_t off = (arr == 0 ? OFF_KH : OFF_KL);
                cp_async16(sb + off + row * APB + ch * 16, gp);
            } else if (f < 2048) {                // v hi/lo -> stage vs
                int f2 = f - 1024;
                int arr = f2 >> 9;
                int rem = f2 & 511;
                int row = rem >> 3, ch = rem & 7;
                size_t base = ((size_t)(j0 + row) * BB + b) * (3 * EE) + hc + 2 * EE + ch * 8;
                const __nv_bfloat16* gp = (arr == 0 ? g_qkv_h : g_qkv_l) + base;
                uint32_t off = OFF_V + vs * VSTG + arr * (64 * APB);
                cp_async16(sb + off + row * APB + ch * 16, gp);
            } else {                              // rband hi/lo
                int f2  = f - 2048;
                int arr = f2 >> 10;
                int rem = f2 & 1023;
                int row = rem >> 3, ch = rem & 7;
                size_t base = ((size_t)(rbase + row) * BB + b) * EE + hc + ch * 8;
                const __nv_bfloat16* gp = (arr == 0 ? g_rp_h : g_rp_l) + base;
                uint32_t off = (arr == 0 ? OFF_RBH : OFF_RBL);
                cp_async16(sb + off + row * APB + ch * 16, gp);
            }
        }
        CP_COMMIT();
    };

    // ---- build qw = q+rw, qr = q+rr as bf16 hi/lo in smem (once) ----
    #pragma unroll
    for (int rep = 0; rep < 2; rep++) {
        int f   = tid + rep * 256;        // 0..511
        int row = f >> 3;                 // 0..63
        int ch  = f & 7;                  // 16B chunk (8 bf16)
        size_t gq = ((size_t)(i0 + row) * BB + b) * (3 * EE) + hc + ch * 8;
        uint4 qh4 = *reinterpret_cast<const uint4*>(g_qkv_h + gq);
        uint4 ql4 = *reinterpret_cast<const uint4*>(g_qkv_l + gq);
        const __nv_bfloat16* qhp = reinterpret_cast<const __nv_bfloat16*>(&qh4);
        const __nv_bfloat16* qlp = reinterpret_cast<const __nv_bfloat16*>(&ql4);
        float4 rw0 = *reinterpret_cast<const float4*>(&g_rw[hc + ch * 8]);
        float4 rw1 = *reinterpret_cast<const float4*>(&g_rw[hc + ch * 8 + 4]);
        float4 rr0 = *reinterpret_cast<const float4*>(&g_rr[hc + ch * 8]);
        float4 rr1 = *reinterpret_cast<const float4*>(&g_rr[hc + ch * 8 + 4]);
        float rwv[8] = {rw0.x, rw0.y, rw0.z, rw0.w, rw1.x, rw1.y, rw1.z, rw1.w};
        float rrv[8] = {rr0.x, rr0.y, rr0.z, rr0.w, rr1.x, rr1.y, rr1.z, rr1.w};
        uint4 owh, owl, orh, orl;
        __nv_bfloat16* pwh = reinterpret_cast<__nv_bfloat16*>(&owh);
        __nv_bfloat16* pwl = reinterpret_cast<__nv_bfloat16*>(&owl);
        __nv_bfloat16* prh = reinterpret_cast<__nv_bfloat16*>(&orh);
        __nv_bfloat16* prl = reinterpret_cast<__nv_bfloat16*>(&orl);
        #pragma unroll
        for (int e = 0; e < 8; e++) {
            float q  = __bfloat162float(qhp[e]) + __bfloat162float(qlp[e]);
            float aw = q + rwv[e];
            float ar = q + rrv[e];
            __nv_bfloat16 hw = __float2bfloat16(aw);
            __nv_bfloat16 hr = __float2bfloat16(ar);
            pwh[e] = hw; pwl[e] = __float2bfloat16(aw - __bfloat162float(hw));
            prh[e] = hr; prl[e] = __float2bfloat16(ar - __bfloat162float(hr));
        }
        uint32_t so = row * APB + ch * 16;
        *reinterpret_cast<uint4*>(smc + OFF_QWH + so) = owh;
        *reinterpret_cast<uint4*>(smc + OFF_QWL + so) = owl;
        *reinterpret_cast<uint4*>(smc + OFF_QRH + so) = orh;
        *reinterpret_cast<uint4*>(smc + OFF_QRL + so) = orl;
    }

    float m_i[4], l_i[4];
    #pragma unroll
    for (int a = 0; a < 4; a++) { m_i[a] = -1e30f; l_i[a] = 0.f; }
    float accO[4][4];
    #pragma unroll
    for (int ni = 0; ni < 4; ni++)
        #pragma unroll
        for (int q = 0; q < 4; q++) accO[ni][q] = 0.f;

    load_tiles(0, 0);

    for (int jt = 0; jt < 16; jt++) {
        CP_WAIT0();
        __syncthreads();   // loads visible; prev PV done; q/frag stores visible

        // ---- S phase: AC + banded BDm via mma (9 tiles per warp) ----
        float acc[9][4];
        #pragma unroll
        for (int t = 0; t < 9; t++)
            #pragma unroll
            for (int q = 0; q < 4; q++) acc[t][q] = 0.f;

        #pragma unroll
        for (int ks = 0; ks < 4; ks++) {
            const int kb = ks * 32;
            uint32_t ro = (m0w + l4) * APB + kb + (lane >> 4) * 16;
            uint32_t ARH[4], ARL[4];
            LDSM4(ARH, sb + OFF_QRH + ro);
            LDSM4(ARL, sb + OFF_QRL + ro);
            if (half == 0) {
                uint32_t AWH[4], AWL[4];
                LDSM4(AWH, sb + OFF_QWH + ro);
                LDSM4(AWL, sb + OFF_QWL + ro);
                #pragma unroll
                for (int ni = 0; ni < 8; ni++) {  // AC tiles
                    uint32_t bo = (ni * 8 + (l4 & 7)) * APB + kb + ((l4 >> 3) & 1) * 16;
                    uint32_t BH[2], BL[2];
                    LDSM2(BH, sb + OFF_KH + bo);
                    LDSM2(BL, sb + OFF_KL + bo);
                    MMA_BF16(acc[ni], AWH, BH);
                    MMA_BF16(acc[ni], AWH, BL);
                    MMA_BF16(acc[ni], AWL, BH);
                }
                {                                 // first live BD tile
                    uint32_t bo = (tb0 * 8 + (l4 & 7)) * APB + kb + ((l4 >> 3) & 1) * 16;
                    uint32_t BH[2], BL[2];
                    LDSM2(BH, sb + OFF_RBH + bo);
                    LDSM2(BL, sb + OFF_RBL + bo);
                    MMA_BF16(acc[8], ARH, BH);
                    MMA_BF16(acc[8], ARH, BL);
                    MMA_BF16(acc[8], ARL, BH);
                }
            } else {
                #pragma unroll
                for (int t = 0; t < 9; t++) {     // BD tiles tb0+1..tb0+9
                    uint32_t bo = ((tb0 + 1 + t) * 8 + (l4 & 7)) * APB
                                + kb + ((l4 >> 3) & 1) * 16;
                    uint32_t BH[2], BL[2];
                    LDSM2(BH, sb + OFF_RBH + bo);
                    LDSM2(BL, sb + OFF_RBL + bo);
                    MMA_BF16(acc[t], ARH, BH);
                    MMA_BF16(acc[t], ARH, BL);
                    MMA_BF16(acc[t], ARL, BH);
                }
            }
        }

        // ---- store S fragments to smem ----
        {
            const int r0 = m0w + (lane >> 2);
            const int cc = (lane & 3) * 2;
            if (half == 0) {
                #pragma unroll
                for (int ni = 0; ni < 8; ni++) {
                    *reinterpret_cast<float2*>(&ACS[r0 * 72 + ni * 8 + cc]) =
                        make_float2(acc[ni][0], acc[ni][1]);
                    *reinterpret_cast<float2*>(&ACS[(r0 + 8) * 72 + ni * 8 + cc]) =
                        make_float2(acc[ni][2], acc[ni][3]);
                }
                *reinterpret_cast<float2*>(&BDS[r0 * 132 + tb0 * 8 + cc]) =
                    make_float2(acc[8][0], acc[8][1]);
                *reinterpret_cast<float2*>(&BDS[(r0 + 8) * 132 + tb0 * 8 + cc]) =
                    make_float2(acc[8][2], acc[8][3]);
            } else {
                #pragma unroll
                for (int t = 0; t < 9; t++) {
                    int tc = (tb0 + 1 + t) * 8;
                    *reinterpret_cast<float2*>(&BDS[r0 * 132 + tc + cc]) =
                        make_float2(acc[t][0], acc[t][1]);
                    *reinterpret_cast<float2*>(&BDS[(r0 + 8) * 132 + tc + cc]) =
                        make_float2(acc[t][2], acc[t][3]);
                }
            }
        }
        __syncthreads();   // frags visible; k/rb now dead -> safe to refill

        // ---- prefetch jt+1 (overlaps softmax + PV) ----
        if (jt + 1 < 16) load_tiles(jt + 1, (jt + 1) & 1);

        // ---- softmax (thread (tx,ty) owns rows ty*4+a, cols tx*4..+3) ----
        #pragma unroll
        for (int a = 0; a < 4; a++) {
            const int i = ty * 4 + a;
            float s[4];
            float mx = -1e30f;
            #pragma unroll
            for (int c = 0; c < 4; c++) {
                const int j = tx * 4 + c;
                float v = ACS[i * 72 + j] + BDS[i * 132 + (j - i + 63)];
                s[c] = v * 0.125f;
                mx = fmaxf(mx, s[c]);
            }
            #pragma unroll
            for (int off = 8; off > 0; off >>= 1)
                mx = fmaxf(mx, __shfl_xor_sync(0xffffffffu, mx, off));
            float mnew = fmaxf(m_i[a], mx);
            float corr = __expf(m_i[a] - mnew);
            float p[4]; float psum = 0.f;
            #pragma unroll
            for (int c = 0; c < 4; c++) {
                p[c] = __expf(s[c] - mnew);
                psum += p[c];
            }
            #pragma unroll
            for (int off = 8; off > 0; off >>= 1)
                psum += __shfl_xor_sync(0xffffffffu, psum, off);
            l_i[a] = l_i[a] * corr + psum;
            m_i[a] = mnew;
            if (tx == 0) rowc[i] = corr;
            __nv_bfloat162 ph0, ph1, pl0, pl1;
            __nv_bfloat16 h0 = __float2bfloat16(p[0]);
            __nv_bfloat16 h1 = __float2bfloat16(p[1]);
            __nv_bfloat16 h2 = __float2bfloat16(p[2]);
            __nv_bfloat16 h3 = __float2bfloat16(p[3]);
            ph0.x = h0; ph0.y = h1; ph1.x = h2; ph1.y = h3;
            pl0.x = __float2bfloat16(p[0] - __bfloat162float(h0));
            pl0.y = __float2bfloat16(p[1] - __bfloat162float(h1));
            pl1.x = __float2bfloat16(p[2] - __bfloat162float(h2));
            pl1.y = __float2bfloat16(p[3] - __bfloat162float(h3));
            uint32_t po = i * APB + tx * 8;
            *reinterpret_cast<__nv_bfloat162*>(smc + OFF_PH + po)     = ph0;
            *reinterpret_cast<__nv_bfloat162*>(smc + OFF_PH + po + 4) = ph1;
            *reinterpret_cast<__nv_bfloat162*>(smc + OFF_PL + po)     = pl0;
            *reinterpret_cast<__nv_bfloat162*>(smc + OFF_PL + po + 4) = pl1;
        }
        __syncthreads();   // p + rowc visible

        // ---- PV: rescale O frags, then O += P.V (v stage jt&1) ----
        {
            const uint32_t vH = sb + OFF_V + (jt & 1) * VSTG;
            const uint32_t vL = vH + 64 * APB;
            float c0 = rowc[m0w + (lane >> 2)];
            float c1 = rowc[m0w + 8 + (lane >> 2)];
            #pragma unroll
            for (int ni = 0; ni < 4; ni++) {
                accO[ni][0] *= c0; accO[ni][1] *= c0;
                accO[ni][2] *= c1; accO[ni][3] *= c1;
            }
            #pragma unroll
            for (int ks = 0; ks < 4; ks++) {
                const int kb = ks * 32;
                uint32_t ro = (m0w + l4) * APB + kb + (lane >> 4) * 16;
                uint32_t PH[4], PL[4];
                LDSM4(PH, sb + OFF_PH + ro);
                LDSM4(PL, sb + OFF_PL + ro);
                #pragma unroll
                for (int ni = 0; ni < 4; ni++) {
                    int d0 = half * 32 + ni * 8;
                    uint32_t vo = (ks * 16 + l4) * APB + d0 * 2;
                    uint32_t BH[2], BL[2];
                    LDSM2T(BH, vH + vo);
                    LDSM2T(BL, vL + vo);
                    MMA_BF16(accO[ni], PH, BH);
                    MMA_BF16(accO[ni], PH, BL);
                    MMA_BF16(accO[ni], PL, BH);
                }
            }
        }
    }

    // ---- write 1/l, then O -> g_ao hi/lo ----
    #pragma unroll
    for (int a = 0; a < 4; a++)
        if (tx == 0) rowi[ty * 4 + a] = 1.0f / l_i[a];
    __syncthreads();

    {
        float i0v = rowi[m0w + (lane >> 2)];
        float i1v = rowi[m0w + 8 + (lane >> 2)];
        int r0 = i0 + m0w + (lane >> 2);
        #pragma unroll
        for (int ni = 0; ni < 4; ni++) {
            int dcol = hc + half * 32 + ni * 8 + (lane & 3) * 2;
            float o00 = accO[ni][0] * i0v, o01 = accO[ni][1] * i0v;
            float o10 = accO[ni][2] * i1v, o11 = accO[ni][3] * i1v;
            size_t b0 = ((size_t)r0 * BB + b) * EE + dcol;
            size_t b1 = ((size_t)(r0 + 8) * BB + b) * EE + dcol;
            __nv_bfloat16 h00 = __float2bfloat16(o00), h01 = __float2bfloat16(o01);
            __nv_bfloat16 h10 = __float2bfloat16(o10), h11 = __float2bfloat16(o11);
            __nv_bfloat162 hv0; hv0.x = h00; hv0.y = h01;
            __nv_bfloat162 hv1; hv1.x = h10; hv1.y = h11;
            __nv_bfloat162 lv0, lv1;
            lv0.x = __float2bfloat16(o00 - __bfloat162float(h00));
            lv0.y = __float2bfloat16(o01 - __bfloat162float(h01));
            lv1.x = __float2bfloat16(o10 - __bfloat162float(h10));
            lv1.y = __float2bfloat16(o11 - __bfloat162float(h11));
            *reinterpret_cast<__nv_bfloat162*>(&g_ao_h[b0]) = hv0;
            *reinterpret_cast<__nv_bfloat162*>(&g_ao_l[b0]) = lv0;
            *reinterpret_cast<__nv_bfloat162*>(&g_ao_h[b1]) = hv1;
            *reinterpret_cast<__nv_bfloat162*>(&g_ao_l[b1]) = lv1;
        }
    }
}

// ---------------------------------------------------------------------------
// Host launcher (graph-capturable: kernel launches only)
// ---------------------------------------------------------------------------
extern "C" void kernel_launch(void* const* d_in, const int* in_sizes, int n_in,
                              void* d_out, int out_size)
{
    const float* input  = (const float*)d_in[0];
    const float* pos    = (const float*)d_in[1];
    const float* factor = (const float*)d_in[2];
    const float* w_in   = (const float*)d_in[3];
    const float* w_pos  = (const float*)d_in[4];
    const float* w_out  = (const float*)d_in[5];
    const float* b_in   = (const float*)d_in[6];
    const float* b_pos  = (const float*)d_in[7];
    const float* b_out  = (const float*)d_in[8];
    const float* rwb    = (const float*)d_in[9];
    const float* rrb    = (const float*)d_in[10];
    float* out = (float*)d_out;

    cudaFuncSetAttribute(attn_mma,
                         cudaFuncAttributeMaxDynamicSharedMemorySize,
                         ATT2_SMEM);
    cudaFuncSetAttribute(hmma_gemm,
                         cudaFuncAttributeMaxDynamicSharedMemorySize,
                         GEMM_SMEM);

    // 1) hypernetwork (W -> bf16 hi/lo) + input/pos split
    hypernet_kernel<<<SEG7 / 256, 256>>>(w_in, w_pos, w_out, b_in, b_pos, b_out,
                                         rwb, rrb, factor);
    convert_kernel<<<NCONV_BLOCKS, 256>>>(input, pos);

    // 2) qkv = input @ W_in^T + b_in   : [2048, 3072] (bf16 hi/lo out)
    hmma_gemm<<<dim3(3072 / 128, TBR / 128), 256, GEMM_SMEM>>>(nullptr, 0);

    // 3) r = pos @ W_pos^T + b_pos     : [4096(pad), 1024] (bf16 hi/lo out)
    hmma_gemm<<<dim3(EE / 128, RPAD / 128), 256, GEMM_SMEM>>>(nullptr, 1);

    // 4) fused relative attention (mma.sync) -> ao (bf16 hi/lo)
    attn_mma<<<dim3(TT / 64, HH, BB), 256, ATT2_SMEM>>>();

    // 5) out = ao @ W_out^T + b_out    : [2048, 1024] -> d_out (fp32)
    hmma_gemm<<<dim3(EE / 128, TBR / 128), 256, GEMM_SMEM>>>(out, 2);
}

// round 10
// speedup vs baseline: 2.8594x; 1.0294x over previous
#include <cuda_runtime.h>
#include <cuda_bf16.h>
#include <cstdint>

// ---------------------------------------------------------------------------
// Problem constants
// ---------------------------------------------------------------------------
#define TT 1024
#define BB 2
#define EE 1024
#define HH 16
#define DD 64
#define RR 2047              // 2T-1
#define TBR (TT*BB)          // 2048 rows of [E]
#define RBR (RR*BB)          // 4094 valid pos rows
#define RPAD 4096            // padded pos rows (multiple of 128)

// ---------------------------------------------------------------------------
// Device scratch (static; no runtime allocation)
// ---------------------------------------------------------------------------
__device__ __align__(16) __nv_bfloat16 g_Win_h [3*EE*EE], g_Win_l [3*EE*EE];
__device__ __align__(16) __nv_bfloat16 g_Wpos_h[EE*EE],   g_Wpos_l[EE*EE];
__device__ __align__(16) __nv_bfloat16 g_Wout_h[EE*EE],   g_Wout_l[EE*EE];
__device__ __align__(16) __nv_bfloat16 g_in_h  [TBR*EE],  g_in_l  [TBR*EE];
__device__ __align__(16) __nv_bfloat16 g_pos_h [(size_t)RPAD*EE], g_pos_l[(size_t)RPAD*EE];
__device__ __align__(16) __nv_bfloat16 g_ao_h  [TBR*EE],  g_ao_l  [TBR*EE];
__device__ __align__(16) __nv_bfloat16 g_qkv_h [(size_t)TBR * 3*EE], g_qkv_l [(size_t)TBR * 3*EE];
__device__ __align__(16) __nv_bfloat16 g_rp_h  [(size_t)RPAD * EE],  g_rp_l  [(size_t)RPAD * EE];
__device__ __align__(16) float g_bin [3*EE];
__device__ __align__(16) float g_bpos[EE];
__device__ __align__(16) float g_bout[EE];
__device__ __align__(16) float g_rw  [EE];
__device__ __align__(16) float g_rr  [EE];

// ---------------------------------------------------------------------------
// Portable PTX helpers (plain sm_103 target: NO tcgen05)
// ---------------------------------------------------------------------------
__device__ __forceinline__ uint32_t smem_u32(const void* p) {
    uint32_t a;
    asm("{ .reg .u64 t; cvta.to.shared.u64 t, %1; cvt.u32.u64 %0, t; }"
        : "=r"(a) : "l"(p));
    return a;
}
__device__ __forceinline__ void cp_async16(uint32_t dst, const void* src) {
    asm volatile("cp.async.cg.shared.global [%0], [%1], 16;"
                 :: "r"(dst), "l"(src) : "memory");
}
#define CP_COMMIT()  asm volatile("cp.async.commit_group;" ::: "memory")
#define CP_WAIT1()   asm volatile("cp.async.wait_group 1;" ::: "memory")
#define CP_WAIT0()   asm volatile("cp.async.wait_group 0;" ::: "memory")

#define LDSM4(r, a) asm volatile( \
    "ldmatrix.sync.aligned.m8n8.x4.shared.b16 {%0,%1,%2,%3}, [%4];" \
    : "=r"((r)[0]), "=r"((r)[1]), "=r"((r)[2]), "=r"((r)[3]) : "r"(a))

#define LDSM2(r, a) asm volatile( \
    "ldmatrix.sync.aligned.m8n8.x2.shared.b16 {%0,%1}, [%2];" \
    : "=r"((r)[0]), "=r"((r)[1]) : "r"(a))

#define LDSM2T(r, a) asm volatile( \
    "ldmatrix.sync.aligned.m8n8.x2.trans.shared.b16 {%0,%1}, [%2];" \
    : "=r"((r)[0]), "=r"((r)[1]) : "r"(a))

#define MMA_BF16(c, a, b) asm volatile( \
    "mma.sync.aligned.m16n8k16.row.col.f32.bf16.bf16.f32 " \
    "{%0,%1,%2,%3}, {%4,%5,%6,%7}, {%8,%9}, {%0,%1,%2,%3};" \
    : "+f"((c)[0]), "+f"((c)[1]), "+f"((c)[2]), "+f"((c)[3]) \
    : "r"((a)[0]), "r"((a)[1]), "r"((a)[2]), "r"((a)[3]), \
      "r"((b)[0]), "r"((b)[1]))

// ---------------------------------------------------------------------------
// Kernel 1: hypernetwork matvec. W segments -> bf16 hi/lo; rest -> fp32.
// ---------------------------------------------------------------------------
#define SEG0 (3*EE*EE)
#define SEG1 (SEG0 + EE*EE)
#define SEG2 (SEG1 + EE*EE)
#define SEG3 (SEG2 + 3*EE)
#define SEG4 (SEG3 + EE)
#define SEG5 (SEG4 + EE)
#define SEG6 (SEG5 + EE)
#define SEG7 (SEG6 + EE)     // total = 5,250,048 = 20508*256

__global__ void hypernet_kernel(const float* __restrict__ w_in,
                                const float* __restrict__ w_pos,
                                const float* __restrict__ w_out,
                                const float* __restrict__ b_in,
                                const float* __restrict__ b_pos,
                                const float* __restrict__ b_out,
                                const float* __restrict__ rwb,
                                const float* __restrict__ rrb,
                                const float* __restrict__ fac)
{
    __shared__ float fs[8];
    if (threadIdx.x < 8) fs[threadIdx.x] = fac[threadIdx.x];
    __syncthreads();

    int idx = blockIdx.x * blockDim.x + threadIdx.x;
    if (idx >= SEG7) return;

    const float* src; int li;
    if      (idx < SEG0) { src = w_in;  li = idx;        }
    else if (idx < SEG1) { src = w_pos; li = idx - SEG0; }
    else if (idx < SEG2) { src = w_out; li = idx - SEG1; }
    else if (idx < SEG3) { src = b_in;  li = idx - SEG2; }
    else if (idx < SEG4) { src = b_pos; li = idx - SEG3; }
    else if (idx < SEG5) { src = b_out; li = idx - SEG4; }
    else if (idx < SEG6) { src = rwb;   li = idx - SEG5; }
    else                 { src = rrb;   li = idx - SEG6; }

    const float4* s4 = reinterpret_cast<const float4*>(src) + (size_t)li * 2;
    float4 a = s4[0];
    float4 b = s4[1];
    float w = a.x*fs[0] + a.y*fs[1] + a.z*fs[2] + a.w*fs[3]
            + b.x*fs[4] + b.y*fs[5] + b.z*fs[6] + b.w*fs[7];

    if (idx < SEG2) {
        __nv_bfloat16 h = __float2bfloat16(w);
        __nv_bfloat16 l = __float2bfloat16(w - __bfloat162float(h));
        if (idx < SEG0)      { g_Win_h [li] = h; g_Win_l [li] = l; }
        else if (idx < SEG1) { g_Wpos_h[li] = h; g_Wpos_l[li] = l; }
        else                 { g_Wout_h[li] = h; g_Wout_l[li] = l; }
    } else {
        float* dst;
        if      (idx < SEG3) dst = g_bin;
        else if (idx < SEG4) dst = g_bpos;
        else if (idx < SEG5) dst = g_bout;
        else if (idx < SEG6) dst = g_rw;
        else                 dst = g_rr;
        dst[li] = w;
    }
}

// ---------------------------------------------------------------------------
// Kernel 1b: split input / pos into bf16 hi/lo (pos padded to 4096 rows)
// ---------------------------------------------------------------------------
#define NIN4  (TBR * EE / 4)          // 524288
#define NPOS4 ((size_t)RPAD * EE / 4) // 1048576
#define NCONV_BLOCKS 6144             // (NIN4+NPOS4)/256

__global__ void convert_kernel(const float* __restrict__ input,
                               const float* __restrict__ pos)
{
    int idx = blockIdx.x * blockDim.x + threadIdx.x;   // float4 index
    float4 v;
    __nv_bfloat16 *dh, *dl;
    size_t o;
    if (idx < NIN4) {
        v = reinterpret_cast<const float4*>(input)[idx];
        dh = g_in_h; dl = g_in_l; o = (size_t)idx * 4;
    } else {
        size_t j = (size_t)idx - NIN4;
        if (j * 4 < (size_t)RBR * EE)
            v = reinterpret_cast<const float4*>(pos)[j];
        else
            v = make_float4(0.f, 0.f, 0.f, 0.f);
        dh = g_pos_h; dl = g_pos_l; o = j * 4;
    }
    __nv_bfloat16 h0 = __float2bfloat16(v.x), h1 = __float2bfloat16(v.y);
    __nv_bfloat16 h2 = __float2bfloat16(v.z), h3 = __float2bfloat16(v.w);
    __nv_bfloat162 hh0; hh0.x = h0; hh0.y = h1;
    __nv_bfloat162 hh1; hh1.x = h2; hh1.y = h3;
    __nv_bfloat162 ll0, ll1;
    ll0.x = __float2bfloat16(v.x - __bfloat162float(h0));
    ll0.y = __float2bfloat16(v.y - __bfloat162float(h1));
    ll1.x = __float2bfloat16(v.z - __bfloat162float(h2));
    ll1.y = __float2bfloat16(v.w - __bfloat162float(h3));
    *reinterpret_cast<__nv_bfloat162*>(&dh[o])     = hh0;
    *reinterpret_cast<__nv_bfloat162*>(&dh[o + 2]) = hh1;
    *reinterpret_cast<__nv_bfloat162*>(&dl[o])     = ll0;
    *reinterpret_cast<__nv_bfloat162*>(&dl[o + 2]) = ll1;
}

// ---------------------------------------------------------------------------
// Kernel 2: HMMA bf16x3 GEMM (NT): C[m][n] = bias[n] + sum_k A[m][k]*B[n][k]
// which==3: FUSED qkv+pos launch (1-D grid, first 384 blocks = qkv tiles,
// next 256 = pos tiles) so the pos GEMM fills the qkv GEMM's tail wave.
// ---------------------------------------------------------------------------
#define BK 32
#define PITCH 80                 // bytes per smem row: 64 data + 16 pad
#define ARR   (128 * PITCH)      // 10240 bytes per tile array
#define STAGE (4 * ARR)          // Ah | Al | Bh | Bl
#define GEMM_SMEM (2 * STAGE)    // 81920

__global__ __launch_bounds__(256, 2)
void hmma_gemm(float* __restrict__ Cext, int which)
{
    int w, bx, by;
    if (which == 3) {
        int id = blockIdx.x;
        if (id < 384) { w = 0; bx = id % 24; by = id / 24; }   // qkv 24x16
        else          { w = 1; int i2 = id - 384; bx = i2 & 7; by = i2 >> 3; } // pos 8x32
    } else {
        w = which; bx = blockIdx.x; by = blockIdx.y;
    }

    const __nv_bfloat16 *Ah, *Al, *Bh, *Bl;
    const float* bias; int ldc;
    __nv_bfloat16 *Ch = nullptr, *Cl = nullptr;
    float* C = nullptr;
    if (w == 0)      { Ah = g_in_h;  Al = g_in_l;  Bh = g_Win_h;  Bl = g_Win_l;
                       bias = g_bin;  Ch = g_qkv_h; Cl = g_qkv_l; ldc = 3*EE; }
    else if (w == 1) { Ah = g_pos_h; Al = g_pos_l; Bh = g_Wpos_h; Bl = g_Wpos_l;
                       bias = g_bpos; Ch = g_rp_h;  Cl = g_rp_l;  ldc = EE; }
    else             { Ah = g_ao_h;  Al = g_ao_l;  Bh = g_Wout_h; Bl = g_Wout_l;
                       bias = g_bout; C = Cext;  ldc = EE; }

    extern __shared__ char smem[];
    const uint32_t sb = smem_u32(smem);

    const int tid  = threadIdx.x;
    const int lane = tid & 31;
    const int wid  = tid >> 5;
    const int wr   = wid >> 1;          // 0..3  (m)
    const int wc   = wid & 1;           // 0..1  (n)
    const int m0   = by * 128;
    const int n0   = bx * 128;

    auto load_chunk = [&](int c, int s) {
        const int kc = c * BK;
        #pragma unroll
        for (int it = 0; it < 8; it++) {
            int f   = tid + it * 256;        // 0..2047
            int arr = f >> 9;                // 0..3
            int rem = f & 511;
            int row = rem >> 2;              // 0..127
            int ch  = rem & 3;               // 16B chunk in row
            uint32_t dst = sb + s * STAGE + arr * ARR + row * PITCH + ch * 16;
            const __nv_bfloat16* gp;
            if      (arr == 0) gp = Ah + (size_t)(m0 + row) * EE + kc + ch * 8;
            else if (arr == 1) gp = Al + (size_t)(m0 + row) * EE + kc + ch * 8;
            else if (arr == 2) gp = Bh + (size_t)(n0 + row) * EE + kc + ch * 8;
            else               gp = Bl + (size_t)(n0 + row) * EE + kc + ch * 8;
            cp_async16(dst, gp);
        }
        CP_COMMIT();
    };

    float acc[2][8][4];
    #pragma unroll
    for (int mi = 0; mi < 2; mi++)
        #pragma unroll
        for (int ni = 0; ni < 8; ni++)
            #pragma unroll
            for (int q = 0; q < 4; q++) acc[mi][ni][q] = 0.f;

    load_chunk(0, 0);

    for (int c = 0; c < 32; c++) {
        const int s = c & 1;
        if (c + 1 < 32) { load_chunk(c + 1, s ^ 1); CP_WAIT1(); }
        else            { CP_WAIT0(); }
        __syncthreads();

        const uint32_t aH = sb + s * STAGE;
        const uint32_t aL = aH + ARR;
        const uint32_t bH = aH + 2 * ARR;
        const uint32_t bL = aH + 3 * ARR;
        const int l4 = lane & 15;

        #pragma unroll
        for (int kk = 0; kk < 2; kk++) {
            const int kb = kk * 32;

            uint32_t AH[2][4], AL[2][4];
            #pragma unroll
            for (int mi = 0; mi < 2; mi++) {
                uint32_t ro = (wr * 32 + mi * 16 + l4) * PITCH + kb + (lane >> 4) * 16;
                LDSM4(AH[mi], aH + ro);
                LDSM4(AL[mi], aL + ro);
            }
            #pragma unroll
            for (int ni = 0; ni < 8; ni++) {
                uint32_t ro = (wc * 64 + ni * 8 + (l4 & 7)) * PITCH
                            + kb + ((l4 >> 3) & 1) * 16;
                uint32_t BH[2], BL[2];
                LDSM2(BH, bH + ro);
                LDSM2(BL, bL + ro);
                #pragma unroll
                for (int mi = 0; mi < 2; mi++) {
                    MMA_BF16(acc[mi][ni], AH[mi], BH);
                    MMA_BF16(acc[mi][ni], AH[mi], BL);
                    MMA_BF16(acc[mi][ni], AL[mi], BH);
                }
            }
        }
        __syncthreads();
    }

    // ---- epilogue ----
    #pragma unroll
    for (int mi = 0; mi < 2; mi++) {
        #pragma unroll
        for (int r2 = 0; r2 < 2; r2++) {
            int grow = m0 + wr * 32 + mi * 16 + (lane >> 2) + r2 * 8;
            #pragma unroll
            for (int ni = 0; ni < 8; ni++) {
                int gcol = n0 + wc * 64 + ni * 8 + (lane & 3) * 2;
                float2 bv = *reinterpret_cast<const float2*>(&bias[gcol]);
                float ox = acc[mi][ni][r2 * 2 + 0] + bv.x;
                float oy = acc[mi][ni][r2 * 2 + 1] + bv.y;
                if (w == 2) {
                    *reinterpret_cast<float2*>(&C[(size_t)grow * ldc + gcol]) =
                        make_float2(ox, oy);
                } else {
                    __nv_bfloat16 hx = __float2bfloat16(ox);
                    __nv_bfloat16 hy = __float2bfloat16(oy);
                    __nv_bfloat162 hv; hv.x = hx; hv.y = hy;
                    __nv_bfloat162 lv;
                    lv.x = __float2bfloat16(ox - __bfloat162float(hx));
                    lv.y = __float2bfloat16(oy - __bfloat162float(hy));
                    *reinterpret_cast<__nv_bfloat162*>(&Ch[(size_t)grow * ldc + gcol]) = hv;
                    *reinterpret_cast<__nv_bfloat162*>(&Cl[(size_t)grow * ldc + gcol]) = lv;
                }
            }
        }
    }
}

// ---------------------------------------------------------------------------
// Kernel 3: MMA flash attention, 512 threads (16 warps) for latency hiding.
// Warp (band = wid>>2, qg = wid&3):
//   S-phase: band owns rows 16b..+15. qg0: AC tiles 0..3; qg1: AC 4..7;
//            qg2: BD tiles tb0..tb0+4; qg3: BD tb0+5..tb0+9  (tb0 = 6-2b).
//   PV:      band rows, qg owns d-quarter (16 cols, 2 n-tiles).
// Softmax: thread (ty=tid>>4 -> 2 rows, tx=tid&15 -> 4 cols); 16-lane shfl.
// Pipeline: k/rb refilled for jt+1 after frag-store sync; v double-buffered.
// ---------------------------------------------------------------------------
#define APB 144                        // bf16 tile row pitch (64*2 + 16 pad)
#define OFF_QWH 0
#define OFF_QWL (OFF_QWH + 64*APB)
#define OFF_QRH (OFF_QWL + 64*APB)
#define OFF_QRL (OFF_QRH + 64*APB)
#define OFF_KH  (OFF_QRL + 64*APB)
#define OFF_KL  (OFF_KH  + 64*APB)
#define OFF_V   (OFF_KL  + 64*APB)     // 2 stages x (VH | VL)
#define VSTG    (2 * 64 * APB)
#define OFF_RBH (OFF_V + 2*VSTG)
#define OFF_RBL (OFF_RBH + 128*APB)
#define OFF_PH  (OFF_RBL + 128*APB)
#define OFF_PL  (OFF_PH  + 64*APB)
#define OFF_ACS (OFF_PL  + 64*APB)     // float[64][72]
#define OFF_BDS (OFF_ACS + 64*72*4)    // float[64][132]
#define OFF_ROW (OFF_BDS + 64*132*4)   // corr[64] + inv[64]
#define ATT2_SMEM (OFF_ROW + 512)      // 200192

__global__ __launch_bounds__(512, 1)
void attn_mma()
{
    extern __shared__ char smc[];
    const uint32_t sb = smem_u32(smc);
    float* ACS  = reinterpret_cast<float*>(smc + OFF_ACS);
    float* BDS  = reinterpret_cast<float*>(smc + OFF_BDS);
    float* rowc = reinterpret_cast<float*>(smc + OFF_ROW);
    float* rowi = reinterpret_cast<float*>(smc + OFF_ROW + 256);

    const int tid  = threadIdx.x;
    const int lane = tid & 31;
    const int wid  = tid >> 5;        // 0..15
    const int tx   = tid & 15;
    const int ty   = tid >> 4;        // 0..31 (2 softmax rows each)
    const int band = wid >> 2;        // 0..3: 16-row band
    const int qg   = wid & 3;         // 0..3: column/work group
    const int m0w  = band * 16;
    const int tb0  = 6 - 2 * band;    // first live BD u-tile for this band
    const int l4   = lane & 15;
    const int it   = blockIdx.x;
    const int h    = blockIdx.y;
    const int b    = blockIdx.z;
    const int i0   = it * 64;
    const int hc   = h * DD;

    // ---- async loader for one jt: k, rb (S-phase), v[vs] (PV) ----
    auto load_tiles = [&](int jt, int vs) {
        const int j0 = jt * 64;
        const int rbase = 1023 + j0 - i0 - 63;
        #pragma unroll
        for (int rep = 0; rep < 8; rep++) {
            int f = tid + rep * 512;              // 0..4095
            if (f < 1024) {                       // k hi/lo
                int arr = f >> 9;
                int rem = f & 511;
                int row = rem >> 3, ch = rem & 7;
                size_t base = ((size_t)(j0 + row) * BB + b) * (3 * EE) + hc + EE + ch * 8;
                const __nv_bfloat16* gp = (arr == 0 ? g_qkv_h : g_qkv_l) + base;
                uint32_t off = (arr == 0 ? OFF_KH : OFF_KL);
                cp_async16(sb + off + row * APB + ch * 16, gp);
            } else if (f < 2048) {                // v hi/lo -> stage vs
                int f2 = f - 1024;
                int arr = f2 >> 9;
                int rem = f2 & 511;
                int row = rem >> 3, ch = rem & 7;
                size_t base = ((size_t)(j0 + row) * BB + b) * (3 * EE) + hc + 2 * EE + ch * 8;
                const __nv_bfloat16* gp = (arr == 0 ? g_qkv_h : g_qkv_l) + base;
                uint32_t off = OFF_V + vs * VSTG + arr * (64 * APB);
                cp_async16(sb + off + row * APB + ch * 16, gp);
            } else {                              // rband hi/lo
                int f2  = f - 2048;
                int arr = f2 >> 10;
                int rem = f2 & 1023;
                int row = rem >> 3, ch = rem & 7;
                size_t base = ((size_t)(rbase + row) * BB + b) * EE + hc + ch * 8;
                const __nv_bfloat16* gp = (arr == 0 ? g_rp_h : g_rp_l) + base;
                uint32_t off = (arr == 0 ? OFF_RBH : OFF_RBL);
                cp_async16(sb + off + row * APB + ch * 16, gp);
            }
        }
        CP_COMMIT();
    };

    // ---- build qw = q+rw, qr = q+rr as bf16 hi/lo in smem (once) ----
    {
        int f   = tid;                    // 0..511
        int row = f >> 3;                 // 0..63
        int ch  = f & 7;                  // 16B chunk (8 bf16)
        size_t gq = ((size_t)(i0 + row) * BB + b) * (3 * EE) + hc + ch * 8;
        uint4 qh4 = *reinterpret_cast<const uint4*>(g_qkv_h + gq);
        uint4 ql4 = *reinterpret_cast<const uint4*>(g_qkv_l + gq);
        const __nv_bfloat16* qhp = reinterpret_cast<const __nv_bfloat16*>(&qh4);
        const __nv_bfloat16* qlp = reinterpret_cast<const __nv_bfloat16*>(&ql4);
        float4 rw0 = *reinterpret_cast<const float4*>(&g_rw[hc + ch * 8]);
        float4 rw1 = *reinterpret_cast<const float4*>(&g_rw[hc + ch * 8 + 4]);
        float4 rr0 = *reinterpret_cast<const float4*>(&g_rr[hc + ch * 8]);
        float4 rr1 = *reinterpret_cast<const float4*>(&g_rr[hc + ch * 8 + 4]);
        float rwv[8] = {rw0.x, rw0.y, rw0.z, rw0.w, rw1.x, rw1.y, rw1.z, rw1.w};
        float rrv[8] = {rr0.x, rr0.y, rr0.z, rr0.w, rr1.x, rr1.y, rr1.z, rr1.w};
        uint4 owh, owl, orh, orl;
        __nv_bfloat16* pwh = reinterpret_cast<__nv_bfloat16*>(&owh);
        __nv_bfloat16* pwl = reinterpret_cast<__nv_bfloat16*>(&owl);
        __nv_bfloat16* prh = reinterpret_cast<__nv_bfloat16*>(&orh);
        __nv_bfloat16* prl = reinterpret_cast<__nv_bfloat16*>(&orl);
        #pragma unroll
        for (int e = 0; e < 8; e++) {
            float q  = __bfloat162float(qhp[e]) + __bfloat162float(qlp[e]);
            float aw = q + rwv[e];
            float ar = q + rrv[e];
            __nv_bfloat16 hw = __float2bfloat16(aw);
            __nv_bfloat16 hr = __float2bfloat16(ar);
            pwh[e] = hw; pwl[e] = __float2bfloat16(aw - __bfloat162float(hw));
            prh[e] = hr; prl[e] = __float2bfloat16(ar - __bfloat162float(hr));
        }
        uint32_t so = row * APB + ch * 16;
        *reinterpret_cast<uint4*>(smc + OFF_QWH + so) = owh;
        *reinterpret_cast<uint4*>(smc + OFF_QWL + so) = owl;
        *reinterpret_cast<uint4*>(smc + OFF_QRH + so) = orh;
        *reinterpret_cast<uint4*>(smc + OFF_QRL + so) = orl;
    }

    float m_i[2], l_i[2];
    #pragma unroll
    for (int a = 0; a < 2; a++) { m_i[a] = -1e30f; l_i[a] = 0.f; }
    float accO[2][4];
    #pragma unroll
    for (int ni = 0; ni < 2; ni++)
        #pragma unroll
        for (int q = 0; q < 4; q++) accO[ni][q] = 0.f;

    load_tiles(0, 0);

    for (int jt = 0; jt < 16; jt++) {
        CP_WAIT0();
        __syncthreads();   // loads visible; prev PV done; q/frag stores visible

        // ---- S phase: per-warp <=5 tiles ----
        float acc[5][4];
        #pragma unroll
        for (int t = 0; t < 5; t++)
            #pragma unroll
            for (int q = 0; q < 4; q++) acc[t][q] = 0.f;

        #pragma unroll
        for (int ks = 0; ks < 4; ks++) {
            const int kb = ks * 32;
            uint32_t ro = (m0w + l4) * APB + kb + (lane >> 4) * 16;
            if (qg < 2) {
                uint32_t AWH[4], AWL[4];
                LDSM4(AWH, sb + OFF_QWH + ro);
                LDSM4(AWL, sb + OFF_QWL + ro);
                #pragma unroll
                for (int ni = 0; ni < 4; ni++) {      // AC tiles qg*4+ni
                    uint32_t bo = ((qg * 4 + ni) * 8 + (l4 & 7)) * APB
                                + kb + ((l4 >> 3) & 1) * 16;
                    uint32_t BH[2], BL[2];
                    LDSM2(BH, sb + OFF_KH + bo);
                    LDSM2(BL, sb + OFF_KL + bo);
                    MMA_BF16(acc[ni], AWH, BH);
                    MMA_BF16(acc[ni], AWH, BL);
                    MMA_BF16(acc[ni], AWL, BH);
                }
            } else {
                uint32_t ARH[4], ARL[4];
                LDSM4(ARH, sb + OFF_QRH + ro);
                LDSM4(ARL, sb + OFF_QRL + ro);
                const int t0 = tb0 + (qg - 2) * 5;
                #pragma unroll
                for (int t = 0; t < 5; t++) {         // BD tiles t0..t0+4
                    uint32_t bo = ((t0 + t) * 8 + (l4 & 7)) * APB
                                + kb + ((l4 >> 3) & 1) * 16;
                    uint32_t BH[2], BL[2];
                    LDSM2(BH, sb + OFF_RBH + bo);
                    LDSM2(BL, sb + OFF_RBL + bo);
                    MMA_BF16(acc[t], ARH, BH);
                    MMA_BF16(acc[t], ARH, BL);
                    MMA_BF16(acc[t], ARL, BH);
                }
            }
        }

        // ---- store S fragments to smem ----
        {
            const int r0 = m0w + (lane >> 2);
            const int cc = (lane & 3) * 2;
            if (qg < 2) {
                #pragma unroll
                for (int ni = 0; ni < 4; ni++) {
                    int col = (qg * 4 + ni) * 8 + cc;
                    *reinterpret_cast<float2*>(&ACS[r0 * 72 + col]) =
                        make_float2(acc[ni][0], acc[ni][1]);
                    *reinterpret_cast<float2*>(&ACS[(r0 + 8) * 72 + col]) =
                        make_float2(acc[ni][2], acc[ni][3]);
                }
            } else {
                const int t0 = tb0 + (qg - 2) * 5;
                #pragma unroll
                for (int t = 0; t < 5; t++) {
                    int col = (t0 + t) * 8 + cc;
                    *reinterpret_cast<float2*>(&BDS[r0 * 132 + col]) =
                        make_float2(acc[t][0], acc[t][1]);
                    *reinterpret_cast<float2*>(&BDS[(r0 + 8) * 132 + col]) =
                        make_float2(acc[t][2], acc[t][3]);
                }
            }
        }
        __syncthreads();   // frags visible; k/rb now dead -> safe to refill

        // ---- prefetch jt+1 (overlaps softmax + PV) ----
        if (jt + 1 < 16) load_tiles(jt + 1, (jt + 1) & 1);

        // ---- softmax: thread owns rows ty*2, ty*2+1; cols tx*4..+3 ----
        #pragma unroll
        for (int a = 0; a < 2; a++) {
            const int i = ty * 2 + a;
            float s[4];
            float mx = -1e30f;
            #pragma unroll
            for (int c = 0; c < 4; c++) {
                const int j = tx * 4 + c;
                float v = ACS[i * 72 + j] + BDS[i * 132 + (j - i + 63)];
                s[c] = v * 0.125f;
                mx = fmaxf(mx, s[c]);
            }
            #pragma unroll
            for (int off = 8; off > 0; off >>= 1)
                mx = fmaxf(mx, __shfl_xor_sync(0xffffffffu, mx, off));
            float mnew = fmaxf(m_i[a], mx);
            float corr = __expf(m_i[a] - mnew);
            float p[4]; float psum = 0.f;
            #pragma unroll
            for (int c = 0; c < 4; c++) {
                p[c] = __expf(s[c] - mnew);
                psum += p[c];
            }
            #pragma unroll
            for (int off = 8; off > 0; off >>= 1)
                psum += __shfl_xor_sync(0xffffffffu, psum, off);
            l_i[a] = l_i[a] * corr + psum;
            m_i[a] = mnew;
            if (tx == 0) rowc[i] = corr;
            __nv_bfloat162 ph0, ph1, pl0, pl1;
            __nv_bfloat16 h0 = __float2bfloat16(p[0]);
            __nv_bfloat16 h1 = __float2bfloat16(p[1]);
            __nv_bfloat16 h2 = __float2bfloat16(p[2]);
            __nv_bfloat16 h3 = __float2bfloat16(p[3]);
            ph0.x = h0; ph0.y = h1; ph1.x = h2; ph1.y = h3;
            pl0.x = __float2bfloat16(p[0] - __bfloat162float(h0));
            pl0.y = __float2bfloat16(p[1] - __bfloat162float(h1));
            pl1.x = __float2bfloat16(p[2] - __bfloat162float(h2));
            pl1.y = __float2bfloat16(p[3] - __bfloat162float(h3));
            uint32_t po = i * APB + tx * 8;
            *reinterpret_cast<__nv_bfloat162*>(smc + OFF_PH + po)     = ph0;
            *reinterpret_cast<__nv_bfloat162*>(smc + OFF_PH + po + 4) = ph1;
            *reinterpret_cast<__nv_bfloat162*>(smc + OFF_PL + po)     = pl0;
            *reinterpret_cast<__nv_bfloat162*>(smc + OFF_PL + po + 4) = pl1;
        }
        __syncthreads();   // p + rowc visible

        // ---- PV: rescale O frags, then O += P.V (v stage jt&1) ----
        {
            const uint32_t vH = sb + OFF_V + (jt & 1) * VSTG;
            const uint32_t vL = vH + 64 * APB;
            float c0 = rowc[m0w + (lane >> 2)];
            float c1 = rowc[m0w + 8 + (lane >> 2)];
            #pragma unroll
            for (int ni = 0; ni < 2; ni++) {
                accO[ni][0] *= c0; accO[ni][1] *= c0;
                accO[ni][2] *= c1; accO[ni][3] *= c1;
            }
            #pragma unroll
            for (int ks = 0; ks < 4; ks++) {
                const int kb = ks * 32;
                uint32_t ro = (m0w + l4) * APB + kb + (lane >> 4) * 16;
                uint32_t PH[4], PL[4];
                LDSM4(PH, sb + OFF_PH + ro);
                LDSM4(PL, sb + OFF_PL + ro);
                #pragma unroll
                for (int ni = 0; ni < 2; ni++) {
                    int d0 = qg * 16 + ni * 8;
                    uint32_t vo = (ks * 16 + l4) * APB + d0 * 2;
                    uint32_t BH[2], BL[2];
                    LDSM2T(BH, vH + vo);
                    LDSM2T(BL, vL + vo);
                    MMA_BF16(accO[ni], PH, BH);
                    MMA_BF16(accO[ni], PH, BL);
                    MMA_BF16(accO[ni], PL, BH);
                }
            }
        }
    }

    // ---- write 1/l, then O -> g_ao hi/lo ----
    #pragma unroll
    for (int a = 0; a < 2; a++)
        if (tx == 0) rowi[ty * 2 + a] = 1.0f / l_i[a];
    __syncthreads();

    {
        float i0v = rowi[m0w + (lane >> 2)];
        float i1v = rowi[m0w + 8 + (lane >> 2)];
        int r0 = i0 + m0w + (lane >> 2);
        #pragma unroll
        for (int ni = 0; ni < 2; ni++) {
            int dcol = hc + qg * 16 + ni * 8 + (lane & 3) * 2;
            float o00 = accO[ni][0] * i0v, o01 = accO[ni][1] * i0v;
            float o10 = accO[ni][2] * i1v, o11 = accO[ni][3] * i1v;
            size_t b0 = ((size_t)r0 * BB + b) * EE + dcol;
            size_t b1 = ((size_t)(r0 + 8) * BB + b) * EE + dcol;
            __nv_bfloat16 h00 = __float2bfloat16(o00), h01 = __float2bfloat16(o01);
            __nv_bfloat16 h10 = __float2bfloat16(o10), h11 = __float2bfloat16(o11);
            __nv_bfloat162 hv0; hv0.x = h00; hv0.y = h01;
            __nv_bfloat162 hv1; hv1.x = h10; hv1.y = h11;
            __nv_bfloat162 lv0, lv1;
            lv0.x = __float2bfloat16(o00 - __bfloat162float(h00));
            lv0.y = __float2bfloat16(o01 - __bfloat162float(h01));
            lv1.x = __float2bfloat16(o10 - __bfloat162float(h10));
            lv1.y = __float2bfloat16(o11 - __bfloat162float(h11));
            *reinterpret_cast<__nv_bfloat162*>(&g_ao_h[b0]) = hv0;
            *reinterpret_cast<__nv_bfloat162*>(&g_ao_l[b0]) = lv0;
            *reinterpret_cast<__nv_bfloat162*>(&g_ao_h[b1]) = hv1;
            *reinterpret_cast<__nv_bfloat162*>(&g_ao_l[b1]) = lv1;
        }
    }
}

// ---------------------------------------------------------------------------
// Host launcher (graph-capturable: kernel launches only)
// ---------------------------------------------------------------------------
extern "C" void kernel_launch(void* const* d_in, const int* in_sizes, int n_in,
                              void* d_out, int out_size)
{
    const float* input  = (const float*)d_in[0];
    const float* pos    = (const float*)d_in[1];
    const float* factor = (const float*)d_in[2];
    const float* w_in   = (const float*)d_in[3];
    const float* w_pos  = (const float*)d_in[4];
    const float* w_out  = (const float*)d_in[5];
    const float* b_in   = (const float*)d_in[6];
    const float* b_pos  = (const float*)d_in[7];
    const float* b_out  = (const float*)d_in[8];
    const float* rwb    = (const float*)d_in[9];
    const float* rrb    = (const float*)d_in[10];
    float* out = (float*)d_out;

    cudaFuncSetAttribute(attn_mma,
                         cudaFuncAttributeMaxDynamicSharedMemorySize,
                         ATT2_SMEM);
    cudaFuncSetAttribute(hmma_gemm,
                         cudaFuncAttributeMaxDynamicSharedMemorySize,
                         GEMM_SMEM);

    // 1) hypernetwork (W -> bf16 hi/lo) + input/pos split
    hypernet_kernel<<<SEG7 / 256, 256>>>(w_in, w_pos, w_out, b_in, b_pos, b_out,
                                         rwb, rrb, factor);
    convert_kernel<<<NCONV_BLOCKS, 256>>>(input, pos);

    // 2+3) FUSED: qkv (384 tiles) + pos (256 tiles) in one launch
    hmma_gemm<<<640, 256, GEMM_SMEM>>>(nullptr, 3);

    // 4) fused relative attention (mma.sync, 512 threads) -> ao (bf16 hi/lo)
    attn_mma<<<dim3(TT / 64, HH, BB), 512, ATT2_SMEM>>>();

    // 5) out = ao @ W_out^T + b_out    : [2048, 1024] -> d_out (fp32)
    hmma_gemm<<<dim3(EE / 128, TBR / 128), 256, GEMM_SMEM>>>(out, 2);
}